// round 5
// baseline (speedup 1.0000x reference)
#include <cuda_runtime.h>
#include <math.h>

// Problem constants (fixed by the dataset)
#define NN   200000
#define BB   1024
#define HH   256
#define H3   768
#define OUTD 128
#define NEG_SLOPE 0.01f

// ---------------- scratch (device globals; no allocation allowed) ----------
__device__ float g_a_src[NN];        // per-node attention source score (loop invariant)
__device__ float g_out [BB * HH];    // GRU state / pooled output
__device__ float g_wsum[BB * HH];    // per-graph alpha-weighted sum of x
__device__ float g_h   [BB * HH];    // elu(agg)
__device__ float g_gi  [BB * H3];
__device__ float g_gh  [BB * H3];
__device__ int   g_segoff[BB + 1];
__device__ float g_was[HH];          // W @ att_src
__device__ float g_wad[HH];          // W @ att_dst

// ---------------- reductions ----------------
__device__ __forceinline__ float warp_sum(float v) {
    #pragma unroll
    for (int o = 16; o; o >>= 1) v += __shfl_xor_sync(0xffffffffu, v, o);
    return v;
}
__device__ __forceinline__ float warp_max(float v) {
    #pragma unroll
    for (int o = 16; o; o >>= 1) v = fmaxf(v, __shfl_xor_sync(0xffffffffu, v, o));
    return v;
}
// 256-thread block reductions using sh[32]
__device__ __forceinline__ float block_sum(float v, float* sh) {
    int l = threadIdx.x & 31, w = threadIdx.x >> 5;
    v = warp_sum(v);
    if (l == 0) sh[w] = v;
    __syncthreads();
    if (w == 0) {
        float r = (l < 8) ? sh[l] : 0.0f;
        r = warp_sum(r);
        if (l == 0) sh[0] = r;
    }
    __syncthreads();
    float r = sh[0];
    __syncthreads();
    return r;
}
__device__ __forceinline__ float block_max(float v, float* sh) {
    int l = threadIdx.x & 31, w = threadIdx.x >> 5;
    v = warp_max(v);
    if (l == 0) sh[w] = v;
    __syncthreads();
    if (w == 0) {
        float r = (l < 8) ? sh[l] : -INFINITY;
        r = warp_max(r);
        if (l == 0) sh[0] = r;
    }
    __syncthreads();
    float r = sh[0];
    __syncthreads();
    return r;
}

__device__ __forceinline__ float sigmoidf_(float x) {
    return 1.0f / (1.0f + __expf(-x));
}

// ---------------- k_prep: w_as = W @ att_src, w_ad = W @ att_dst -----------
__global__ void k_prep(const float* __restrict__ W,
                       const float* __restrict__ att_src,
                       const float* __restrict__ att_dst) {
    int w = threadIdx.x >> 5, l = threadIdx.x & 31;
    int row = blockIdx.x * 8 + w;              // 32 blocks * 8 warps = 256 rows
    const float* Wr = W + (long)row * HH;
    float ps = 0.f, pd = 0.f;
    for (int j = l; j < HH; j += 32) {
        float v = Wr[j];
        ps += v * att_src[j];
        pd += v * att_dst[j];
    }
    ps = warp_sum(ps); pd = warp_sum(pd);
    if (l == 0) { g_was[row] = ps; g_wad[row] = pd; }
}

// ---------------- k_segoff: lower_bound per graph id -----------------------
__global__ void k_segoff(const int* __restrict__ batch, int n) {
    int j = blockIdx.x * blockDim.x + threadIdx.x;
    if (j > BB) return;
    int lo = 0, hi = n;
    while (lo < hi) {
        int mid = (lo + hi) >> 1;
        if (batch[mid] < j) lo = mid + 1; else hi = mid;
    }
    g_segoff[j] = lo;
}

// ---------------- k_pass0: out = segment_sum(x), a_src = x . w_as ----------
__global__ void k_pass0(const float* __restrict__ x) {
    __shared__ float red[8][HH];
    int b = blockIdx.x;
    int tid = threadIdx.x, w = tid >> 5, l = tid & 31;
    int s = g_segoff[b], e = g_segoff[b + 1];

    float was_r[8];
    #pragma unroll
    for (int j = 0; j < 8; j++) was_r[j] = g_was[l + 32 * j];

    float acc[8];
    #pragma unroll
    for (int j = 0; j < 8; j++) acc[j] = 0.f;

    for (int r = s + w; r < e; r += 8) {
        const float* xr = x + (long)r * HH;
        float p = 0.f;
        #pragma unroll
        for (int j = 0; j < 8; j++) {
            float v = xr[l + 32 * j];
            acc[j] += v;
            p += v * was_r[j];
        }
        p = warp_sum(p);
        if (l == 0) g_a_src[r] = p;
    }
    #pragma unroll
    for (int j = 0; j < 8; j++) red[w][l + 32 * j] = acc[j];
    __syncthreads();
    float sum = 0.f;
    #pragma unroll
    for (int ww = 0; ww < 8; ww++) sum += red[ww][tid];
    g_out[(long)b * HH + tid] = sum;
}

// ---------------- k_attn: softmax over segment + weighted sum of x ---------
__global__ void k_attn(const float* __restrict__ x) {
    __shared__ float sh[32];
    __shared__ float red[8][HH];
    int b = blockIdx.x;
    int tid = threadIdx.x, w = tid >> 5, l = tid & 31;
    int s = g_segoff[b], e = g_segoff[b + 1];

    // a_dst_b = out[b] . w_ad
    float adst = block_sum(g_out[(long)b * HH + tid] * g_wad[tid], sh);

    // pass 1: max of leaky(a_src + a_dst)
    float m = -INFINITY;
    for (int r = s + tid; r < e; r += 256) {
        float ev = g_a_src[r] + adst;
        ev = ev > 0.f ? ev : NEG_SLOPE * ev;
        m = fmaxf(m, ev);
    }
    m = block_max(m, sh);

    // pass 2: denom
    float d = 0.f;
    for (int r = s + tid; r < e; r += 256) {
        float ev = g_a_src[r] + adst;
        ev = ev > 0.f ? ev : NEG_SLOPE * ev;
        d += __expf(ev - m);
    }
    d = block_sum(d, sh);
    float inv = (e > s) ? 1.0f / d : 0.0f;

    // pass 3: weighted sum of x rows
    float acc[8];
    #pragma unroll
    for (int j = 0; j < 8; j++) acc[j] = 0.f;
    for (int r = s + w; r < e; r += 8) {
        float ev = g_a_src[r] + adst;
        ev = ev > 0.f ? ev : NEG_SLOPE * ev;
        float al = __expf(ev - m) * inv;
        const float* xr = x + (long)r * HH;
        #pragma unroll
        for (int j = 0; j < 8; j++) acc[j] += al * xr[l + 32 * j];
    }
    #pragma unroll
    for (int j = 0; j < 8; j++) red[w][l + 32 * j] = acc[j];
    __syncthreads();
    float sum = 0.f;
    #pragma unroll
    for (int ww = 0; ww < 8; ww++) sum += red[ww][tid];
    g_wsum[(long)b * HH + tid] = sum;
}

// ---------------- generic tiled fp32 GEMM: C = A * B (+bias, epilogue) -----
// TRANSB=false: B[k*N + n]; TRANSB=true: B[n*K + k]
// EPI: 0 = bias only, 1 = bias + elu
template <bool TRANSB, int EPI>
__global__ void gemm_k(const float* __restrict__ A, const float* __restrict__ Bw,
                       const float* __restrict__ bias, float* __restrict__ C,
                       int M, int Nn, int K) {
    const int BM = 64, BN = 64, BK = 16;
    __shared__ float As[BK][BM + 4];
    __shared__ float Bs[BK][BN + 4];
    int bm = blockIdx.y * BM, bn = blockIdx.x * BN;
    int tx = threadIdx.x & 15, ty = threadIdx.x >> 4;

    float acc[4][4];
    #pragma unroll
    for (int i = 0; i < 4; i++)
        #pragma unroll
        for (int j = 0; j < 4; j++) acc[i][j] = 0.f;

    for (int k0 = 0; k0 < K; k0 += BK) {
        #pragma unroll
        for (int q = threadIdx.x; q < BM * BK; q += 256) {
            int row = q >> 4, kk = q & 15;
            As[kk][row] = A[(long)(bm + row) * K + k0 + kk];
        }
        #pragma unroll
        for (int q = threadIdx.x; q < BK * BN; q += 256) {
            if (TRANSB) {
                int col = q >> 4, kk = q & 15;
                Bs[kk][col] = Bw[(long)(bn + col) * K + k0 + kk];
            } else {
                int kk = q >> 6, col = q & 63;
                Bs[kk][col] = Bw[(long)(k0 + kk) * Nn + bn + col];
            }
        }
        __syncthreads();
        #pragma unroll
        for (int kk = 0; kk < BK; kk++) {
            float a4[4], b4[4];
            #pragma unroll
            for (int i = 0; i < 4; i++) a4[i] = As[kk][ty * 4 + i];
            #pragma unroll
            for (int j = 0; j < 4; j++) b4[j] = Bs[kk][tx * 4 + j];
            #pragma unroll
            for (int i = 0; i < 4; i++)
                #pragma unroll
                for (int j = 0; j < 4; j++) acc[i][j] += a4[i] * b4[j];
        }
        __syncthreads();
    }
    #pragma unroll
    for (int i = 0; i < 4; i++) {
        int m = bm + ty * 4 + i;
        #pragma unroll
        for (int j = 0; j < 4; j++) {
            int n = bn + tx * 4 + j;
            float v = acc[i][j] + bias[n];
            if (EPI == 1) v = (v > 0.f) ? v : expm1f(v);
            C[(long)m * Nn + n] = v;
        }
    }
}

// ---------------- k_gate: GRU gate combine + silu --------------------------
__global__ void k_gate() {
    int idx = blockIdx.x * 256 + threadIdx.x;      // BB*HH total
    int b = idx >> 8, j = idx & 255;
    const float* gi = g_gi + (long)b * H3;
    const float* gh = g_gh + (long)b * H3;
    float r = sigmoidf_(gi[j] + gh[j]);
    float z = sigmoidf_(gi[HH + j] + gh[HH + j]);
    float n = tanhf(gi[2 * HH + j] + r * gh[2 * HH + j]);
    float o = g_out[idx];
    float v = (1.0f - z) * n + z * o;
    g_out[idx] = v * sigmoidf_(v);                 // silu
}

// ---------------- launch --------------------------------------------------
extern "C" void kernel_launch(void* const* d_in, const int* in_sizes, int n_in,
                              void* d_out, int out_size) {
    const float* x        = (const float*)d_in[0];
    const int*   batch    = (const int*)  d_in[1];
    const float* W        = (const float*)d_in[2];
    const float* att_src  = (const float*)d_in[3];
    const float* att_dst  = (const float*)d_in[4];
    const float* bias_gat = (const float*)d_in[5];
    const float* W_ih     = (const float*)d_in[6];
    const float* W_hh     = (const float*)d_in[7];
    const float* b_ih     = (const float*)d_in[8];
    const float* b_hh     = (const float*)d_in[9];
    const float* W_lin    = (const float*)d_in[10];
    const float* b_lin    = (const float*)d_in[11];
    float* out = (float*)d_out;

    int n = in_sizes[1];   // number of nodes (batch vector length)

    float *p_out, *p_wsum, *p_h, *p_gi, *p_gh;
    cudaGetSymbolAddress((void**)&p_out,  g_out);
    cudaGetSymbolAddress((void**)&p_wsum, g_wsum);
    cudaGetSymbolAddress((void**)&p_h,    g_h);
    cudaGetSymbolAddress((void**)&p_gi,   g_gi);
    cudaGetSymbolAddress((void**)&p_gh,   g_gh);

    k_prep<<<32, 256>>>(W, att_src, att_dst);
    k_segoff<<<(BB + 1 + 255) / 256, 256>>>(batch, n);
    k_pass0<<<BB, 256>>>(x);

    for (int t = 0; t < 2; t++) {
        k_attn<<<BB, 256>>>(x);
        // h = elu(wsum @ W + bias_gat)
        gemm_k<false, 1><<<dim3(HH / 64, BB / 64), 256>>>(p_wsum, W, bias_gat, p_h, BB, HH, HH);
        // gi = h @ W_ih^T + b_ih ; gh = out @ W_hh^T + b_hh
        gemm_k<true, 0><<<dim3(H3 / 64, BB / 64), 256>>>(p_h,   W_ih, b_ih, p_gi, BB, H3, HH);
        gemm_k<true, 0><<<dim3(H3 / 64, BB / 64), 256>>>(p_out, W_hh, b_hh, p_gh, BB, H3, HH);
        k_gate<<<BB * HH / 256, 256>>>();
    }
    // y = out @ W_lin + b_lin
    gemm_k<false, 0><<<dim3(OUTD / 64, BB / 64), 256>>>(p_out, W_lin, b_lin, out, BB, OUTD, HH);
}

// round 8
// speedup vs baseline: 1.4047x; 1.4047x over previous
#include <cuda_runtime.h>
#include <math.h>

// Problem constants (fixed by the dataset)
#define NN   200000
#define BB   1024
#define HH   256
#define H3   768
#define OUTD 128
#define NEG_SLOPE 0.01f

// ---------------- scratch (device globals; no allocation allowed) ----------
__device__ float g_a_src[NN];        // per-node attention source score (loop invariant)
__device__ float g_out [BB * HH];    // GRU state / pooled output
__device__ float g_wsum[BB * HH];    // per-graph alpha-weighted sum of x
__device__ float g_h   [BB * HH];    // elu(agg)
__device__ float g_gi  [BB * H3];
__device__ float g_gh  [BB * H3];
__device__ int   g_segoff[BB + 1];
__device__ float g_was[HH];          // W @ att_src
__device__ float g_wad[HH];          // W @ att_dst

// ---------------- reductions ----------------
__device__ __forceinline__ float warp_sum(float v) {
    #pragma unroll
    for (int o = 16; o; o >>= 1) v += __shfl_xor_sync(0xffffffffu, v, o);
    return v;
}
__device__ __forceinline__ float warp_max(float v) {
    #pragma unroll
    for (int o = 16; o; o >>= 1) v = fmaxf(v, __shfl_xor_sync(0xffffffffu, v, o));
    return v;
}
// 256-thread block reductions using sh[32]
__device__ __forceinline__ float block_sum(float v, float* sh) {
    int l = threadIdx.x & 31, w = threadIdx.x >> 5;
    v = warp_sum(v);
    if (l == 0) sh[w] = v;
    __syncthreads();
    if (w == 0) {
        float r = (l < 8) ? sh[l] : 0.0f;
        r = warp_sum(r);
        if (l == 0) sh[0] = r;
    }
    __syncthreads();
    float r = sh[0];
    __syncthreads();
    return r;
}
__device__ __forceinline__ float block_max(float v, float* sh) {
    int l = threadIdx.x & 31, w = threadIdx.x >> 5;
    v = warp_max(v);
    if (l == 0) sh[w] = v;
    __syncthreads();
    if (w == 0) {
        float r = (l < 8) ? sh[l] : -INFINITY;
        r = warp_max(r);
        if (l == 0) sh[0] = r;
    }
    __syncthreads();
    float r = sh[0];
    __syncthreads();
    return r;
}

__device__ __forceinline__ float sigmoidf_(float x) {
    return 1.0f / (1.0f + __expf(-x));
}

// ---------------- k_prep: w_as = W @ att_src, w_ad = W @ att_dst -----------
__global__ void k_prep(const float* __restrict__ W,
                       const float* __restrict__ att_src,
                       const float* __restrict__ att_dst) {
    int w = threadIdx.x >> 5, l = threadIdx.x & 31;
    int row = blockIdx.x * 8 + w;              // 32 blocks * 8 warps = 256 rows
    const float* Wr = W + (long)row * HH;
    float ps = 0.f, pd = 0.f;
    for (int j = l; j < HH; j += 32) {
        float v = Wr[j];
        ps += v * att_src[j];
        pd += v * att_dst[j];
    }
    ps = warp_sum(ps); pd = warp_sum(pd);
    if (l == 0) { g_was[row] = ps; g_wad[row] = pd; }
}

// ---------------- k_segoff: lower_bound per graph id -----------------------
__global__ void k_segoff(const int* __restrict__ batch, int n) {
    int j = blockIdx.x * blockDim.x + threadIdx.x;
    if (j > BB) return;
    int lo = 0, hi = n;
    while (lo < hi) {
        int mid = (lo + hi) >> 1;
        if (batch[mid] < j) lo = mid + 1; else hi = mid;
    }
    g_segoff[j] = lo;
}

// ---------------- k_pass0: out = segment_sum(x), a_src = x . w_as ----------
// float4-vectorized: warp per row, lane covers cols [4l,4l+4) and [128+4l, ...)
__global__ void __launch_bounds__(256) k_pass0(const float* __restrict__ x) {
    __shared__ __align__(16) float red[8 * HH];   // [8 warps][256 cols]
    int b = blockIdx.x;
    int tid = threadIdx.x, w = tid >> 5, l = tid & 31;
    int s = g_segoff[b], e = g_segoff[b + 1];

    const float4* was4 = (const float4*)g_was;
    float4 wa = was4[l], wb = was4[l + 32];

    float4 acc0 = make_float4(0.f, 0.f, 0.f, 0.f);
    float4 acc1 = make_float4(0.f, 0.f, 0.f, 0.f);

    for (int r = s + w; r < e; r += 8) {
        const float4* xr = (const float4*)(x + (long)r * HH);
        float4 a = xr[l], c = xr[l + 32];
        acc0.x += a.x; acc0.y += a.y; acc0.z += a.z; acc0.w += a.w;
        acc1.x += c.x; acc1.y += c.y; acc1.z += c.z; acc1.w += c.w;
        float p = a.x * wa.x + a.y * wa.y + a.z * wa.z + a.w * wa.w
                + c.x * wb.x + c.y * wb.y + c.z * wb.z + c.w * wb.w;
        p = warp_sum(p);
        if (l == 0) g_a_src[r] = p;
    }
    float4* redw = (float4*)(red + w * HH);
    redw[l] = acc0;
    redw[l + 32] = acc1;
    __syncthreads();
    float sum = 0.f;
    #pragma unroll
    for (int ww = 0; ww < 8; ww++) sum += red[ww * HH + tid];
    g_out[(long)b * HH + tid] = sum;
}

// ---------------- attn body: softmax over segment + weighted sum of x ------
// sm must provide 2080 floats: red[8][256] then sh[32]
__device__ __forceinline__ void attn_body(const float* __restrict__ x, float* sm) {
    float* shr = sm + 8 * HH;
    int b = blockIdx.x;
    int tid = threadIdx.x, w = tid >> 5, l = tid & 31;
    int s = g_segoff[b], e = g_segoff[b + 1];

    // a_dst_b = out[b] . w_ad
    float adst = block_sum(g_out[(long)b * HH + tid] * g_wad[tid], shr);

    // pass 1: max of leaky(a_src + a_dst)
    float m = -INFINITY;
    for (int r = s + tid; r < e; r += 256) {
        float ev = g_a_src[r] + adst;
        ev = ev > 0.f ? ev : NEG_SLOPE * ev;
        m = fmaxf(m, ev);
    }
    m = block_max(m, shr);

    // pass 2: denom
    float d = 0.f;
    for (int r = s + tid; r < e; r += 256) {
        float ev = g_a_src[r] + adst;
        ev = ev > 0.f ? ev : NEG_SLOPE * ev;
        d += __expf(ev - m);
    }
    d = block_sum(d, shr);
    float inv = (e > s) ? 1.0f / d : 0.0f;

    // pass 3: weighted sum of x rows (float4)
    float4 acc0 = make_float4(0.f, 0.f, 0.f, 0.f);
    float4 acc1 = make_float4(0.f, 0.f, 0.f, 0.f);
    for (int r = s + w; r < e; r += 8) {
        float ev = g_a_src[r] + adst;
        ev = ev > 0.f ? ev : NEG_SLOPE * ev;
        float al = __expf(ev - m) * inv;
        const float4* xr = (const float4*)(x + (long)r * HH);
        float4 a = xr[l], c = xr[l + 32];
        acc0.x += al * a.x; acc0.y += al * a.y; acc0.z += al * a.z; acc0.w += al * a.w;
        acc1.x += al * c.x; acc1.y += al * c.y; acc1.z += al * c.z; acc1.w += al * c.w;
    }
    float4* redw = (float4*)(sm + w * HH);
    redw[l] = acc0;
    redw[l + 32] = acc1;
    __syncthreads();
    float sum = 0.f;
    #pragma unroll
    for (int ww = 0; ww < 8; ww++) sum += sm[ww * HH + tid];
    g_wsum[(long)b * HH + tid] = sum;
}

// ---------------- tiled fp32 GEMM body: C = A * B (+bias, epilogue) --------
// TRANSB=false: B[k*Nn + n]; TRANSB=true: B[n*K + k]
// EPI: 0 = bias only, 1 = bias + elu. Requires blockDim == (BM/4)*(BN/4).
template <int BM, int BN, int BK, bool TRANSB, int EPI>
__device__ __forceinline__ void gemm_body(
    const float* __restrict__ A, const float* __restrict__ Bw,
    const float* __restrict__ bias, float* __restrict__ C,
    int Nn, int K, int bm, int bn, float* As_, float* Bs_) {

    const int TH = (BM / 4) * (BN / 4);
    const int LDA = BM + 4, LDB = BN + 4;
    int tid = threadIdx.x;
    int tx = tid % (BN / 4), ty = tid / (BN / 4);

    float acc[4][4];
    #pragma unroll
    for (int i = 0; i < 4; i++)
        #pragma unroll
        for (int j = 0; j < 4; j++) acc[i][j] = 0.f;

    for (int k0 = 0; k0 < K; k0 += BK) {
        // load A tile (row-major source) with float4, transpose into As[kk][row]
        #pragma unroll
        for (int q = tid; q < BM * BK / 4; q += TH) {
            int row = q / (BK / 4), kf = q % (BK / 4);
            float4 v = *(const float4*)(A + (long)(bm + row) * K + k0 + kf * 4);
            As_[(kf * 4 + 0) * LDA + row] = v.x;
            As_[(kf * 4 + 1) * LDA + row] = v.y;
            As_[(kf * 4 + 2) * LDA + row] = v.z;
            As_[(kf * 4 + 3) * LDA + row] = v.w;
        }
        if (TRANSB) {
            #pragma unroll
            for (int q = tid; q < BN * BK / 4; q += TH) {
                int col = q / (BK / 4), kf = q % (BK / 4);
                float4 v = *(const float4*)(Bw + (long)(bn + col) * K + k0 + kf * 4);
                Bs_[(kf * 4 + 0) * LDB + col] = v.x;
                Bs_[(kf * 4 + 1) * LDB + col] = v.y;
                Bs_[(kf * 4 + 2) * LDB + col] = v.z;
                Bs_[(kf * 4 + 3) * LDB + col] = v.w;
            }
        } else {
            #pragma unroll
            for (int q = tid; q < BK * BN / 4; q += TH) {
                int kk = q / (BN / 4), cf = q % (BN / 4);
                float4 v = *(const float4*)(Bw + (long)(k0 + kk) * Nn + bn + cf * 4);
                *(float4*)(Bs_ + kk * LDB + cf * 4) = v;
            }
        }
        __syncthreads();
        #pragma unroll
        for (int kk = 0; kk < BK; kk++) {
            float a4[4], b4[4];
            #pragma unroll
            for (int i = 0; i < 4; i++) a4[i] = As_[kk * LDA + ty * 4 + i];
            #pragma unroll
            for (int j = 0; j < 4; j++) b4[j] = Bs_[kk * LDB + tx * 4 + j];
            #pragma unroll
            for (int i = 0; i < 4; i++)
                #pragma unroll
                for (int j = 0; j < 4; j++) acc[i][j] += a4[i] * b4[j];
        }
        __syncthreads();
    }
    #pragma unroll
    for (int i = 0; i < 4; i++) {
        int m = bm + ty * 4 + i;
        #pragma unroll
        for (int j = 0; j < 4; j++) {
            int n = bn + tx * 4 + j;
            float v = acc[i][j] + bias[n];
            if (EPI == 1) v = (v > 0.f) ? v : expm1f(v);
            C[(long)m * Nn + n] = v;
        }
    }
}

// ---------------- fused: attention pass + independent gh GEMM --------------
// blocks [0, BB): attention softmax/aggregation (DRAM-bound)
// blocks [BB, BB+192): gh = out @ W_hh^T + b_hh (compute-bound, overlaps)
__global__ void __launch_bounds__(256) k_attn_gh(
    const float* __restrict__ x,
    const float* __restrict__ W_hh, const float* __restrict__ b_hh) {
    __shared__ __align__(16) float sm[2 * 16 * 68];  // 2176 floats >= 2080 attn use
    if (blockIdx.x < BB) {
        attn_body(x, sm);
    } else {
        int g = blockIdx.x - BB;                 // 192 blocks: 16 x 12
        int bn = (g % (H3 / 64)) * 64;
        int bm = (g / (H3 / 64)) * 64;
        gemm_body<64, 64, 16, true, 0>(g_out, W_hh, b_hh, g_gh,
                                       H3, HH, bm, bn, sm, sm + 16 * 68);
    }
}

// ---------------- h = elu(wsum @ W + bias_gat), 32x32 tiles ---------------
__global__ void __launch_bounds__(64) k_hgemm(
    const float* __restrict__ W, const float* __restrict__ bias) {
    __shared__ __align__(16) float sm[2 * 16 * 36];
    gemm_body<32, 32, 16, false, 1>(g_wsum, W, bias, g_h,
                                    HH, HH, blockIdx.y * 32, blockIdx.x * 32,
                                    sm, sm + 16 * 36);
}

// ---------------- gi = h @ W_ih^T + b_ih, 64x64 tiles ----------------------
__global__ void __launch_bounds__(256) k_gigemm(
    const float* __restrict__ W_ih, const float* __restrict__ b_ih) {
    __shared__ __align__(16) float sm[2 * 16 * 68];
    gemm_body<64, 64, 16, true, 0>(g_h, W_ih, b_ih, g_gi,
                                   H3, HH, blockIdx.y * 64, blockIdx.x * 64,
                                   sm, sm + 16 * 68);
}

// ---------------- final: y = out @ W_lin + b_lin, 32x32 tiles --------------
__global__ void __launch_bounds__(64) k_fingemm(
    const float* __restrict__ W_lin, const float* __restrict__ b_lin,
    float* __restrict__ C) {
    __shared__ __align__(16) float sm[2 * 16 * 36];
    gemm_body<32, 32, 16, false, 0>(g_out, W_lin, b_lin, C,
                                    OUTD, HH, blockIdx.y * 32, blockIdx.x * 32,
                                    sm, sm + 16 * 36);
}

// ---------------- k_gate: GRU gate combine + silu --------------------------
__global__ void k_gate() {
    int idx = blockIdx.x * 256 + threadIdx.x;      // BB*HH total
    int b = idx >> 8, j = idx & 255;
    const float* gi = g_gi + (long)b * H3;
    const float* gh = g_gh + (long)b * H3;
    float r = sigmoidf_(gi[j] + gh[j]);
    float z = sigmoidf_(gi[HH + j] + gh[HH + j]);
    float n = tanhf(gi[2 * HH + j] + r * gh[2 * HH + j]);
    float o = g_out[idx];
    float v = (1.0f - z) * n + z * o;
    g_out[idx] = v * sigmoidf_(v);                 // silu
}

// ---------------- launch --------------------------------------------------
extern "C" void kernel_launch(void* const* d_in, const int* in_sizes, int n_in,
                              void* d_out, int out_size) {
    const float* x        = (const float*)d_in[0];
    const int*   batch    = (const int*)  d_in[1];
    const float* W        = (const float*)d_in[2];
    const float* att_src  = (const float*)d_in[3];
    const float* att_dst  = (const float*)d_in[4];
    const float* bias_gat = (const float*)d_in[5];
    const float* W_ih     = (const float*)d_in[6];
    const float* W_hh     = (const float*)d_in[7];
    const float* b_ih     = (const float*)d_in[8];
    const float* b_hh     = (const float*)d_in[9];
    const float* W_lin    = (const float*)d_in[10];
    const float* b_lin    = (const float*)d_in[11];
    float* out = (float*)d_out;

    int n = in_sizes[1];   // number of nodes (batch vector length)

    k_prep<<<32, 256>>>(W, att_src, att_dst);
    k_segoff<<<(BB + 1 + 255) / 256, 256>>>(batch, n);
    k_pass0<<<BB, 256>>>(x);

    for (int t = 0; t < 2; t++) {
        // attention pass fused with the independent gh GEMM (overlap mem + fma)
        k_attn_gh<<<BB + (BB / 64) * (H3 / 64), 256>>>(x, W_hh, b_hh);
        // h = elu(wsum @ W + bias_gat)
        k_hgemm<<<dim3(HH / 32, BB / 32), 64>>>(W, bias_gat);
        // gi = h @ W_ih^T + b_ih
        k_gigemm<<<dim3(H3 / 64, BB / 64), 256>>>(W_ih, b_ih);
        k_gate<<<BB * HH / 256, 256>>>();
    }
    // y = out @ W_lin + b_lin
    k_fingemm<<<dim3(OUTD / 32, BB / 32), 64>>>(W_lin, b_lin, out);
}

// round 9
// speedup vs baseline: 1.7584x; 1.2518x over previous
#include <cuda_runtime.h>
#include <math.h>
#include <stdint.h>

// Problem constants (fixed by the dataset)
#define NN   200000
#define BB   1024
#define HH   256
#define H3   768
#define OUTD 128
#define NEG_SLOPE 0.01f

// ---------------- scratch (device globals; no allocation allowed) ----------
__device__ float g_a_src[NN];        // per-node attention source score (loop invariant)
__device__ float g_out [BB * HH];    // GRU state / pooled output
__device__ float g_wsum[BB * HH];    // per-graph alpha-weighted sum of x
__device__ float g_h   [BB * HH];    // elu(agg)
__device__ float g_gi  [BB * H3];
__device__ float g_gh  [BB * H3];
__device__ int   g_segoff[BB + 1];
__device__ float g_was[HH];          // W @ att_src
__device__ float g_wad[HH];          // W @ att_dst

// ---------------- reductions ----------------
__device__ __forceinline__ float warp_sum(float v) {
    #pragma unroll
    for (int o = 16; o; o >>= 1) v += __shfl_xor_sync(0xffffffffu, v, o);
    return v;
}
__device__ __forceinline__ float warp_max(float v) {
    #pragma unroll
    for (int o = 16; o; o >>= 1) v = fmaxf(v, __shfl_xor_sync(0xffffffffu, v, o));
    return v;
}
// 256-thread block reductions using sh[32]
__device__ __forceinline__ float block_sum(float v, float* sh) {
    int l = threadIdx.x & 31, w = threadIdx.x >> 5;
    v = warp_sum(v);
    if (l == 0) sh[w] = v;
    __syncthreads();
    if (w == 0) {
        float r = (l < 8) ? sh[l] : 0.0f;
        r = warp_sum(r);
        if (l == 0) sh[0] = r;
    }
    __syncthreads();
    float r = sh[0];
    __syncthreads();
    return r;
}
__device__ __forceinline__ float block_max(float v, float* sh) {
    int l = threadIdx.x & 31, w = threadIdx.x >> 5;
    v = warp_max(v);
    if (l == 0) sh[w] = v;
    __syncthreads();
    if (w == 0) {
        float r = (l < 8) ? sh[l] : -INFINITY;
        r = warp_max(r);
        if (l == 0) sh[0] = r;
    }
    __syncthreads();
    float r = sh[0];
    __syncthreads();
    return r;
}

__device__ __forceinline__ float sigmoidf_(float x) {
    return 1.0f / (1.0f + __expf(-x));
}

// ---------------- k_prep: w_as = W @ att_src, w_ad = W @ att_dst -----------
__global__ void k_prep(const float* __restrict__ W,
                       const float* __restrict__ att_src,
                       const float* __restrict__ att_dst) {
    int w = threadIdx.x >> 5, l = threadIdx.x & 31;
    int row = blockIdx.x * 8 + w;              // 32 blocks * 8 warps = 256 rows
    const float* Wr = W + (long)row * HH;
    float ps = 0.f, pd = 0.f;
    for (int j = l; j < HH; j += 32) {
        float v = Wr[j];
        ps += v * att_src[j];
        pd += v * att_dst[j];
    }
    ps = warp_sum(ps); pd = warp_sum(pd);
    if (l == 0) { g_was[row] = ps; g_wad[row] = pd; }
}

// ---------------- k_segoff: lower_bound per graph id -----------------------
__global__ void k_segoff(const int* __restrict__ batch, int n) {
    int j = blockIdx.x * blockDim.x + threadIdx.x;
    if (j > BB) return;
    int lo = 0, hi = n;
    while (lo < hi) {
        int mid = (lo + hi) >> 1;
        if (batch[mid] < j) lo = mid + 1; else hi = mid;
    }
    g_segoff[j] = lo;
}

// ---------------- k_pass0: out = segment_sum(x), a_src = x . w_as ----------
// float4-vectorized, 2x unrolled for MLP. Warp per row, 8 warps stride rows.
__global__ void __launch_bounds__(256) k_pass0(const float* __restrict__ x) {
    __shared__ __align__(16) float red[8 * HH];   // [8 warps][256 cols]
    int b = blockIdx.x;
    int tid = threadIdx.x, w = tid >> 5, l = tid & 31;
    int s = g_segoff[b], e = g_segoff[b + 1];

    const float4* was4 = (const float4*)g_was;
    float4 wa = was4[l], wb = was4[l + 32];

    float4 acc0 = make_float4(0.f, 0.f, 0.f, 0.f);
    float4 acc1 = make_float4(0.f, 0.f, 0.f, 0.f);

    int r = s + w;
    for (; r + 8 < e; r += 16) {
        const float4* x0 = (const float4*)(x + (long)r * HH);
        const float4* x1 = (const float4*)(x + (long)(r + 8) * HH);
        float4 a0 = x0[l], c0 = x0[l + 32];
        float4 a1 = x1[l], c1 = x1[l + 32];
        acc0.x += a0.x + a1.x; acc0.y += a0.y + a1.y;
        acc0.z += a0.z + a1.z; acc0.w += a0.w + a1.w;
        acc1.x += c0.x + c1.x; acc1.y += c0.y + c1.y;
        acc1.z += c0.z + c1.z; acc1.w += c0.w + c1.w;
        float p0 = a0.x * wa.x + a0.y * wa.y + a0.z * wa.z + a0.w * wa.w
                 + c0.x * wb.x + c0.y * wb.y + c0.z * wb.z + c0.w * wb.w;
        float p1 = a1.x * wa.x + a1.y * wa.y + a1.z * wa.z + a1.w * wa.w
                 + c1.x * wb.x + c1.y * wb.y + c1.z * wb.z + c1.w * wb.w;
        p0 = warp_sum(p0);
        p1 = warp_sum(p1);
        if (l == 0) { g_a_src[r] = p0; g_a_src[r + 8] = p1; }
    }
    if (r < e) {
        const float4* x0 = (const float4*)(x + (long)r * HH);
        float4 a0 = x0[l], c0 = x0[l + 32];
        acc0.x += a0.x; acc0.y += a0.y; acc0.z += a0.z; acc0.w += a0.w;
        acc1.x += c0.x; acc1.y += c0.y; acc1.z += c0.z; acc1.w += c0.w;
        float p0 = a0.x * wa.x + a0.y * wa.y + a0.z * wa.z + a0.w * wa.w
                 + c0.x * wb.x + c0.y * wb.y + c0.z * wb.z + c0.w * wb.w;
        p0 = warp_sum(p0);
        if (l == 0) g_a_src[r] = p0;
    }
    float4* redw = (float4*)(red + w * HH);
    redw[l] = acc0;
    redw[l + 32] = acc1;
    __syncthreads();
    float sum = 0.f;
    #pragma unroll
    for (int ww = 0; ww < 8; ww++) sum += red[ww * HH + tid];
    g_out[(long)b * HH + tid] = sum;
}

// ---------------- k_attn: online softmax over segment + weighted x sum -----
__global__ void __launch_bounds__(256) k_attn(const float* __restrict__ x) {
    __shared__ __align__(16) float red[8 * HH];
    __shared__ float shr[32];
    int b = blockIdx.x;
    int tid = threadIdx.x, w = tid >> 5, l = tid & 31;
    int s = g_segoff[b], e = g_segoff[b + 1];

    // a_dst_b = out[b] . w_ad
    float adst = block_sum(g_out[(long)b * HH + tid] * g_wad[tid], shr);

    // single pass: per-thread online (max, sum)
    float m = -INFINITY, d = 0.f;
    for (int r = s + tid; r < e; r += 256) {
        float ev = g_a_src[r] + adst;
        ev = ev > 0.f ? ev : NEG_SLOPE * ev;
        float mn = fmaxf(m, ev);
        d = d * __expf(m - mn) + __expf(ev - mn);
        m = mn;
    }
    float M = block_max(m, shr);
    float dd = (d > 0.f) ? d * __expf(m - M) : 0.f;
    float D = block_sum(dd, shr);
    float inv = (e > s) ? 1.0f / D : 0.0f;

    // weighted sum of x rows (float4, 2x unroll)
    float4 acc0 = make_float4(0.f, 0.f, 0.f, 0.f);
    float4 acc1 = make_float4(0.f, 0.f, 0.f, 0.f);
    int r = s + w;
    for (; r + 8 < e; r += 16) {
        float e0 = g_a_src[r] + adst;
        float e1 = g_a_src[r + 8] + adst;
        e0 = e0 > 0.f ? e0 : NEG_SLOPE * e0;
        e1 = e1 > 0.f ? e1 : NEG_SLOPE * e1;
        float al0 = __expf(e0 - M) * inv;
        float al1 = __expf(e1 - M) * inv;
        const float4* x0 = (const float4*)(x + (long)r * HH);
        const float4* x1 = (const float4*)(x + (long)(r + 8) * HH);
        float4 a0 = x0[l], c0 = x0[l + 32];
        float4 a1 = x1[l], c1 = x1[l + 32];
        acc0.x += al0 * a0.x + al1 * a1.x; acc0.y += al0 * a0.y + al1 * a1.y;
        acc0.z += al0 * a0.z + al1 * a1.z; acc0.w += al0 * a0.w + al1 * a1.w;
        acc1.x += al0 * c0.x + al1 * c1.x; acc1.y += al0 * c0.y + al1 * c1.y;
        acc1.z += al0 * c0.z + al1 * c1.z; acc1.w += al0 * c0.w + al1 * c1.w;
    }
    if (r < e) {
        float e0 = g_a_src[r] + adst;
        e0 = e0 > 0.f ? e0 : NEG_SLOPE * e0;
        float al0 = __expf(e0 - M) * inv;
        const float4* x0 = (const float4*)(x + (long)r * HH);
        float4 a0 = x0[l], c0 = x0[l + 32];
        acc0.x += al0 * a0.x; acc0.y += al0 * a0.y;
        acc0.z += al0 * a0.z; acc0.w += al0 * a0.w;
        acc1.x += al0 * c0.x; acc1.y += al0 * c0.y;
        acc1.z += al0 * c0.z; acc1.w += al0 * c0.w;
    }
    float4* redw = (float4*)(red + w * HH);
    redw[l] = acc0;
    redw[l + 32] = acc1;
    __syncthreads();
    float sum = 0.f;
    #pragma unroll
    for (int ww = 0; ww < 8; ww++) sum += red[ww * HH + tid];
    g_wsum[(long)b * HH + tid] = sum;
}

// ================= tf32 tensor-core GEMM =================================
// C[M=1024, Nn] = A[M, 256] * B (+bias, epilogue), BM=BN=64, BK=16,
// 128 threads = 4 warps (2x2), warp tile 32x32 via mma.m16n8k8.tf32.
// TRANSB=true : B stored [Nn, 256] row-major (i.e. op is A @ B^T)
// TRANSB=false: B stored [256, Nn] row-major
#define LDT 20   // padded smem row stride (conflict-free quad pattern)

__device__ __forceinline__ uint32_t tf32_(float x) {
    uint32_t r;
    asm("cvt.rna.tf32.f32 %0, %1;" : "=r"(r) : "f"(x));
    return r;
}
__device__ __forceinline__ void mma8(float* c, const uint32_t* a, const uint32_t* b) {
    asm("mma.sync.aligned.m16n8k8.row.col.f32.tf32.tf32.f32 "
        "{%0,%1,%2,%3}, {%4,%5,%6,%7}, {%8,%9}, {%0,%1,%2,%3};"
        : "+f"(c[0]), "+f"(c[1]), "+f"(c[2]), "+f"(c[3])
        : "r"(a[0]), "r"(a[1]), "r"(a[2]), "r"(a[3]), "r"(b[0]), "r"(b[1]));
}

template <int Nn, bool TRANSB, int EPI>
__device__ __forceinline__ void mma_gemm_body(
    const float* __restrict__ A, const float* __restrict__ Bw,
    const float* __restrict__ bias, float* __restrict__ C,
    int bm, int bn, uint32_t* As, uint32_t* Bs) {

    const int K = HH;
    int tid = threadIdx.x, ln = tid & 31, w = tid >> 5;
    int wm = (w >> 1) * 32, wn = (w & 1) * 32;

    float acc[2][4][4];
    #pragma unroll
    for (int i = 0; i < 2; i++)
        #pragma unroll
        for (int j = 0; j < 4; j++)
            #pragma unroll
            for (int q = 0; q < 4; q++) acc[i][j][q] = 0.f;

    for (int k0 = 0; k0 < K; k0 += 16) {
        // A tile: 64 rows x 16 k  (row = tid>>1, each thread 2 float4)
        {
            int row = tid >> 1;
            const float4* src = (const float4*)(A + (long)(bm + row) * K + k0) + (tid & 1) * 2;
            float4 v0 = src[0], v1 = src[1];
            uint32_t* dst = As + row * LDT + (tid & 1) * 8;
            dst[0] = tf32_(v0.x); dst[1] = tf32_(v0.y); dst[2] = tf32_(v0.z); dst[3] = tf32_(v0.w);
            dst[4] = tf32_(v1.x); dst[5] = tf32_(v1.y); dst[6] = tf32_(v1.z); dst[7] = tf32_(v1.w);
        }
        // B tile -> Bs[n][k]
        if (TRANSB) {
            int row = tid >> 1;
            const float4* src = (const float4*)(Bw + (long)(bn + row) * K + k0) + (tid & 1) * 2;
            float4 v0 = src[0], v1 = src[1];
            uint32_t* dst = Bs + row * LDT + (tid & 1) * 8;
            dst[0] = tf32_(v0.x); dst[1] = tf32_(v0.y); dst[2] = tf32_(v0.z); dst[3] = tf32_(v0.w);
            dst[4] = tf32_(v1.x); dst[5] = tf32_(v1.y); dst[6] = tf32_(v1.z); dst[7] = tf32_(v1.w);
        } else {
            #pragma unroll
            for (int q = tid; q < 16 * 16; q += 128) {
                int k = q >> 4, f4 = q & 15;
                float4 v = *(const float4*)(Bw + (long)(k0 + k) * Nn + bn + f4 * 4);
                Bs[(f4 * 4 + 0) * LDT + k] = tf32_(v.x);
                Bs[(f4 * 4 + 1) * LDT + k] = tf32_(v.y);
                Bs[(f4 * 4 + 2) * LDT + k] = tf32_(v.z);
                Bs[(f4 * 4 + 3) * LDT + k] = tf32_(v.w);
            }
        }
        __syncthreads();
        #pragma unroll
        for (int ks = 0; ks < 16; ks += 8) {
            uint32_t af[2][4], bf[4][2];
            #pragma unroll
            for (int mi = 0; mi < 2; mi++) {
                int mr = wm + mi * 16 + (ln >> 2);
                af[mi][0] = As[mr * LDT + ks + (ln & 3)];
                af[mi][1] = As[(mr + 8) * LDT + ks + (ln & 3)];
                af[mi][2] = As[mr * LDT + ks + 4 + (ln & 3)];
                af[mi][3] = As[(mr + 8) * LDT + ks + 4 + (ln & 3)];
            }
            #pragma unroll
            for (int ni = 0; ni < 4; ni++) {
                int nr = wn + ni * 8 + (ln >> 2);
                bf[ni][0] = Bs[nr * LDT + ks + (ln & 3)];
                bf[ni][1] = Bs[nr * LDT + ks + 4 + (ln & 3)];
            }
            #pragma unroll
            for (int mi = 0; mi < 2; mi++)
                #pragma unroll
                for (int ni = 0; ni < 4; ni++)
                    mma8(acc[mi][ni], af[mi], bf[ni]);
        }
        __syncthreads();
    }
    // epilogue
    #pragma unroll
    for (int mi = 0; mi < 2; mi++) {
        #pragma unroll
        for (int ni = 0; ni < 4; ni++) {
            int m = bm + wm + mi * 16 + (ln >> 2);
            int n = bn + wn + ni * 8 + (ln & 3) * 2;
            float b0 = bias[n], b1 = bias[n + 1];
            float v0 = acc[mi][ni][0] + b0, v1 = acc[mi][ni][1] + b1;
            float v2 = acc[mi][ni][2] + b0, v3 = acc[mi][ni][3] + b1;
            if (EPI == 1) {
                v0 = (v0 > 0.f) ? v0 : expm1f(v0);
                v1 = (v1 > 0.f) ? v1 : expm1f(v1);
                v2 = (v2 > 0.f) ? v2 : expm1f(v2);
                v3 = (v3 > 0.f) ? v3 : expm1f(v3);
            }
            *(float2*)(C + (long)m * Nn + n)       = make_float2(v0, v1);
            *(float2*)(C + (long)(m + 8) * Nn + n) = make_float2(v2, v3);
        }
    }
}

// ---- fused: h = elu(wsum@W + bias_gat)  [64 blocks] ----
// ----        gh = out@W_hh^T + b_hh      [192 blocks] (independent) ----
__global__ void __launch_bounds__(128) k_h_gh(
    const float* __restrict__ W, const float* __restrict__ bias_gat,
    const float* __restrict__ W_hh, const float* __restrict__ b_hh) {
    __shared__ __align__(16) uint32_t sm[2 * 64 * LDT];
    if (blockIdx.x < 64) {
        int g = blockIdx.x;
        mma_gemm_body<HH, false, 1>(g_wsum, W, bias_gat, g_h,
                                    (g >> 2) * 64, (g & 3) * 64, sm, sm + 64 * LDT);
    } else {
        int g = blockIdx.x - 64;
        mma_gemm_body<H3, true, 0>(g_out, W_hh, b_hh, g_gh,
                                   (g / 12) * 64, (g % 12) * 64, sm, sm + 64 * LDT);
    }
}

// ---- gi = h @ W_ih^T + b_ih  [192 blocks] ----
__global__ void __launch_bounds__(128) k_gi(
    const float* __restrict__ W_ih, const float* __restrict__ b_ih) {
    __shared__ __align__(16) uint32_t sm[2 * 64 * LDT];
    int g = blockIdx.x;
    mma_gemm_body<H3, true, 0>(g_h, W_ih, b_ih, g_gi,
                               (g / 12) * 64, (g % 12) * 64, sm, sm + 64 * LDT);
}

// ---- y = out @ W_lin + b_lin  [32 blocks] ----
__global__ void __launch_bounds__(128) k_fin(
    const float* __restrict__ W_lin, const float* __restrict__ b_lin,
    float* __restrict__ C) {
    __shared__ __align__(16) uint32_t sm[2 * 64 * LDT];
    int g = blockIdx.x;
    mma_gemm_body<OUTD, false, 0>(g_out, W_lin, b_lin, C,
                                  (g >> 1) * 64, (g & 1) * 64, sm, sm + 64 * LDT);
}

// ---------------- k_gate: GRU gate combine + silu --------------------------
__global__ void k_gate() {
    int idx = blockIdx.x * 256 + threadIdx.x;      // BB*HH total
    int b = idx >> 8, j = idx & 255;
    const float* gi = g_gi + (long)b * H3;
    const float* gh = g_gh + (long)b * H3;
    float r = sigmoidf_(gi[j] + gh[j]);
    float z = sigmoidf_(gi[HH + j] + gh[HH + j]);
    float n = tanhf(gi[2 * HH + j] + r * gh[2 * HH + j]);
    float o = g_out[idx];
    float v = (1.0f - z) * n + z * o;
    g_out[idx] = v * sigmoidf_(v);                 // silu
}

// ---------------- launch --------------------------------------------------
extern "C" void kernel_launch(void* const* d_in, const int* in_sizes, int n_in,
                              void* d_out, int out_size) {
    const float* x        = (const float*)d_in[0];
    const int*   batch    = (const int*)  d_in[1];
    const float* W        = (const float*)d_in[2];
    const float* att_src  = (const float*)d_in[3];
    const float* att_dst  = (const float*)d_in[4];
    const float* bias_gat = (const float*)d_in[5];
    const float* W_ih     = (const float*)d_in[6];
    const float* W_hh     = (const float*)d_in[7];
    const float* b_ih     = (const float*)d_in[8];
    const float* b_hh     = (const float*)d_in[9];
    const float* W_lin    = (const float*)d_in[10];
    const float* b_lin    = (const float*)d_in[11];
    float* out = (float*)d_out;

    int n = in_sizes[1];   // number of nodes (batch vector length)

    k_prep<<<32, 256>>>(W, att_src, att_dst);
    k_segoff<<<(BB + 1 + 255) / 256, 256>>>(batch, n);
    k_pass0<<<BB, 256>>>(x);

    for (int t = 0; t < 2; t++) {
        k_attn<<<BB, 256>>>(x);                    // wsum (needs out, a_src)
        k_h_gh<<<64 + 192, 128>>>(W, bias_gat, W_hh, b_hh);  // h + gh (indep)
        k_gi<<<192, 128>>>(W_ih, b_ih);            // gi (needs h)
        k_gate<<<BB * HH / 256, 256>>>();          // out update
    }
    k_fin<<<32, 128>>>(W_lin, b_lin, out);         // final projection
}

// round 10
// speedup vs baseline: 1.7960x; 1.0214x over previous
#include <cuda_runtime.h>
#include <math.h>
#include <stdint.h>

// Problem constants (fixed by the dataset)
#define NN   200000
#define BB   1024
#define HH   256
#define H3   768
#define OUTD 128
#define NEG_SLOPE 0.01f

// ---------------- scratch (device globals; no allocation allowed) ----------
__device__ float g_a_src[NN];        // per-node attention source score (loop invariant)
__device__ float g_out [BB * HH];    // GRU state / pooled output
__device__ float g_wsum[BB * HH];    // per-graph alpha-weighted sum of x
__device__ float g_h   [BB * HH];    // elu(agg)
__device__ float g_gi  [BB * H3];
__device__ float g_gh  [BB * H3];
__device__ int   g_segoff[BB + 1];
__device__ float g_was[HH];          // W @ att_src
__device__ float g_wad[HH];          // W @ att_dst

// ---------------- reductions ----------------
__device__ __forceinline__ float warp_sum(float v) {
    #pragma unroll
    for (int o = 16; o; o >>= 1) v += __shfl_xor_sync(0xffffffffu, v, o);
    return v;
}
__device__ __forceinline__ float warp_max(float v) {
    #pragma unroll
    for (int o = 16; o; o >>= 1) v = fmaxf(v, __shfl_xor_sync(0xffffffffu, v, o));
    return v;
}
// 256-thread block reductions using sh[32]
__device__ __forceinline__ float block_sum(float v, float* sh) {
    int l = threadIdx.x & 31, w = threadIdx.x >> 5;
    v = warp_sum(v);
    if (l == 0) sh[w] = v;
    __syncthreads();
    if (w == 0) {
        float r = (l < 8) ? sh[l] : 0.0f;
        r = warp_sum(r);
        if (l == 0) sh[0] = r;
    }
    __syncthreads();
    float r = sh[0];
    __syncthreads();
    return r;
}
__device__ __forceinline__ float block_max(float v, float* sh) {
    int l = threadIdx.x & 31, w = threadIdx.x >> 5;
    v = warp_max(v);
    if (l == 0) sh[w] = v;
    __syncthreads();
    if (w == 0) {
        float r = (l < 8) ? sh[l] : -INFINITY;
        r = warp_max(r);
        if (l == 0) sh[0] = r;
    }
    __syncthreads();
    float r = sh[0];
    __syncthreads();
    return r;
}

__device__ __forceinline__ float sigmoidf_(float x) {
    return 1.0f / (1.0f + __expf(-x));
}

// ---------------- k_prep: w_as = W @ att_src, w_ad = W @ att_dst -----------
__global__ void k_prep(const float* __restrict__ W,
                       const float* __restrict__ att_src,
                       const float* __restrict__ att_dst) {
    int w = threadIdx.x >> 5, l = threadIdx.x & 31;
    int row = blockIdx.x * 8 + w;              // 32 blocks * 8 warps = 256 rows
    const float* Wr = W + (long)row * HH;
    float ps = 0.f, pd = 0.f;
    for (int j = l; j < HH; j += 32) {
        float v = Wr[j];
        ps += v * att_src[j];
        pd += v * att_dst[j];
    }
    ps = warp_sum(ps); pd = warp_sum(pd);
    if (l == 0) { g_was[row] = ps; g_wad[row] = pd; }
}

// ---------------- k_segoff: lower_bound per graph id -----------------------
__global__ void k_segoff(const int* __restrict__ batch, int n) {
    int j = blockIdx.x * blockDim.x + threadIdx.x;
    if (j > BB) return;
    int lo = 0, hi = n;
    while (lo < hi) {
        int mid = (lo + hi) >> 1;
        if (batch[mid] < j) lo = mid + 1; else hi = mid;
    }
    g_segoff[j] = lo;
}

// ---------------- softmax + weighted-sum core (shared by both kernels) -----
// Requires: red[8*HH] shared, shr[32] shared, adst computed. Writes g_wsum[b].
__device__ __forceinline__ void attn_core(const float* __restrict__ x,
                                          int b, int s, int e, float adst,
                                          float* red, float* shr) {
    int tid = threadIdx.x, w = tid >> 5, l = tid & 31;

    // single pass over a_src: per-thread online (max, sum)
    float m = -INFINITY, d = 0.f;
    for (int r = s + tid; r < e; r += 256) {
        float ev = g_a_src[r] + adst;
        ev = ev > 0.f ? ev : NEG_SLOPE * ev;
        float mn = fmaxf(m, ev);
        d = d * __expf(m - mn) + __expf(ev - mn);
        m = mn;
    }
    float M = block_max(m, shr);
    float dd = (d > 0.f) ? d * __expf(m - M) : 0.f;
    float D = block_sum(dd, shr);
    float inv = (e > s) ? 1.0f / D : 0.0f;

    // weighted sum of x rows (float4, 2x unroll)
    float4 acc0 = make_float4(0.f, 0.f, 0.f, 0.f);
    float4 acc1 = make_float4(0.f, 0.f, 0.f, 0.f);
    int r = s + w;
    for (; r + 8 < e; r += 16) {
        float e0 = g_a_src[r] + adst;
        float e1 = g_a_src[r + 8] + adst;
        e0 = e0 > 0.f ? e0 : NEG_SLOPE * e0;
        e1 = e1 > 0.f ? e1 : NEG_SLOPE * e1;
        float al0 = __expf(e0 - M) * inv;
        float al1 = __expf(e1 - M) * inv;
        const float4* x0 = (const float4*)(x + (long)r * HH);
        const float4* x1 = (const float4*)(x + (long)(r + 8) * HH);
        float4 a0 = x0[l], c0 = x0[l + 32];
        float4 a1 = x1[l], c1 = x1[l + 32];
        acc0.x += al0 * a0.x + al1 * a1.x; acc0.y += al0 * a0.y + al1 * a1.y;
        acc0.z += al0 * a0.z + al1 * a1.z; acc0.w += al0 * a0.w + al1 * a1.w;
        acc1.x += al0 * c0.x + al1 * c1.x; acc1.y += al0 * c0.y + al1 * c1.y;
        acc1.z += al0 * c0.z + al1 * c1.z; acc1.w += al0 * c0.w + al1 * c1.w;
    }
    if (r < e) {
        float e0 = g_a_src[r] + adst;
        e0 = e0 > 0.f ? e0 : NEG_SLOPE * e0;
        float al0 = __expf(e0 - M) * inv;
        const float4* x0 = (const float4*)(x + (long)r * HH);
        float4 a0 = x0[l], c0 = x0[l + 32];
        acc0.x += al0 * a0.x; acc0.y += al0 * a0.y;
        acc0.z += al0 * a0.z; acc0.w += al0 * a0.w;
        acc1.x += al0 * c0.x; acc1.y += al0 * c0.y;
        acc1.z += al0 * c0.z; acc1.w += al0 * c0.w;
    }
    float4* redw = (float4*)(red + w * HH);
    redw[l] = acc0;
    redw[l + 32] = acc1;
    __syncthreads();
    float sum = 0.f;
    #pragma unroll
    for (int ww = 0; ww < 8; ww++) sum += red[ww * HH + tid];
    g_wsum[(long)b * HH + tid] = sum;
}

// ---------------- k_pass0_attn: fused pool + t=0 attention -----------------
// Sweep1: out[b] = segment_sum(x), a_src = x.w_as (DRAM). Sweep2 (attn_core)
// re-reads the segment while it is still L2-resident.
__global__ void __launch_bounds__(256) k_pass0_attn(const float* __restrict__ x) {
    __shared__ __align__(16) float red[8 * HH];   // [8 warps][256 cols]
    __shared__ float shr[32];
    int b = blockIdx.x;
    int tid = threadIdx.x, w = tid >> 5, l = tid & 31;
    int s = g_segoff[b], e = g_segoff[b + 1];

    const float4* was4 = (const float4*)g_was;
    float4 wa = was4[l], wb = was4[l + 32];

    float4 acc0 = make_float4(0.f, 0.f, 0.f, 0.f);
    float4 acc1 = make_float4(0.f, 0.f, 0.f, 0.f);

    int r = s + w;
    for (; r + 8 < e; r += 16) {
        const float4* x0 = (const float4*)(x + (long)r * HH);
        const float4* x1 = (const float4*)(x + (long)(r + 8) * HH);
        float4 a0 = x0[l], c0 = x0[l + 32];
        float4 a1 = x1[l], c1 = x1[l + 32];
        acc0.x += a0.x + a1.x; acc0.y += a0.y + a1.y;
        acc0.z += a0.z + a1.z; acc0.w += a0.w + a1.w;
        acc1.x += c0.x + c1.x; acc1.y += c0.y + c1.y;
        acc1.z += c0.z + c1.z; acc1.w += c0.w + c1.w;
        float p0 = a0.x * wa.x + a0.y * wa.y + a0.z * wa.z + a0.w * wa.w
                 + c0.x * wb.x + c0.y * wb.y + c0.z * wb.z + c0.w * wb.w;
        float p1 = a1.x * wa.x + a1.y * wa.y + a1.z * wa.z + a1.w * wa.w
                 + c1.x * wb.x + c1.y * wb.y + c1.z * wb.z + c1.w * wb.w;
        p0 = warp_sum(p0);
        p1 = warp_sum(p1);
        if (l == 0) { g_a_src[r] = p0; g_a_src[r + 8] = p1; }
    }
    if (r < e) {
        const float4* x0 = (const float4*)(x + (long)r * HH);
        float4 a0 = x0[l], c0 = x0[l + 32];
        acc0.x += a0.x; acc0.y += a0.y; acc0.z += a0.z; acc0.w += a0.w;
        acc1.x += c0.x; acc1.y += c0.y; acc1.z += c0.z; acc1.w += c0.w;
        float p0 = a0.x * wa.x + a0.y * wa.y + a0.z * wa.z + a0.w * wa.w
                 + c0.x * wb.x + c0.y * wb.y + c0.z * wb.z + c0.w * wb.w;
        p0 = warp_sum(p0);
        if (l == 0) g_a_src[r] = p0;
    }
    float4* redw = (float4*)(red + w * HH);
    redw[l] = acc0;
    redw[l + 32] = acc1;
    __syncthreads();
    float sum = 0.f;
    #pragma unroll
    for (int ww = 0; ww < 8; ww++) sum += red[ww * HH + tid];
    g_out[(long)b * HH + tid] = sum;

    // adst from the locally computed pooled sum (no extra global pass)
    float adst = block_sum(sum * g_wad[tid], shr);
    // __syncthreads inside block_sum orders our g_a_src stores for the block

    attn_core(x, b, s, e, adst, red, shr);
}

// ---------------- k_attn_rev: t=1 attention, reversed segment order --------
// Reverse order exploits the L2 tail left by the previous full x pass.
__global__ void __launch_bounds__(256, 6) k_attn_rev(const float* __restrict__ x) {
    __shared__ __align__(16) float red[8 * HH];
    __shared__ float shr[32];
    int b = (BB - 1) - blockIdx.x;
    int tid = threadIdx.x;
    int s = g_segoff[b], e = g_segoff[b + 1];

    float adst = block_sum(g_out[(long)b * HH + tid] * g_wad[tid], shr);
    attn_core(x, b, s, e, adst, red, shr);
}

// ================= tf32 tensor-core GEMM =================================
// C[M=1024, Nn] = A[M, 256] * B (+bias, epilogue), BM=BN=64, BK=16,
// 128 threads = 4 warps (2x2), warp tile 32x32 via mma.m16n8k8.tf32.
// TRANSB=true : B stored [Nn, 256] row-major (i.e. op is A @ B^T)
// TRANSB=false: B stored [256, Nn] row-major
#define LDT 20   // padded smem row stride (conflict-free quad pattern)

__device__ __forceinline__ uint32_t tf32_(float x) {
    uint32_t r;
    asm("cvt.rna.tf32.f32 %0, %1;" : "=r"(r) : "f"(x));
    return r;
}
__device__ __forceinline__ void mma8(float* c, const uint32_t* a, const uint32_t* b) {
    asm("mma.sync.aligned.m16n8k8.row.col.f32.tf32.tf32.f32 "
        "{%0,%1,%2,%3}, {%4,%5,%6,%7}, {%8,%9}, {%0,%1,%2,%3};"
        : "+f"(c[0]), "+f"(c[1]), "+f"(c[2]), "+f"(c[3])
        : "r"(a[0]), "r"(a[1]), "r"(a[2]), "r"(a[3]), "r"(b[0]), "r"(b[1]));
}

template <int Nn, bool TRANSB, int EPI>
__device__ __forceinline__ void mma_gemm_body(
    const float* __restrict__ A, const float* __restrict__ Bw,
    const float* __restrict__ bias, float* __restrict__ C,
    int bm, int bn, uint32_t* As, uint32_t* Bs) {

    const int K = HH;
    int tid = threadIdx.x, ln = tid & 31, w = tid >> 5;
    int wm = (w >> 1) * 32, wn = (w & 1) * 32;

    float acc[2][4][4];
    #pragma unroll
    for (int i = 0; i < 2; i++)
        #pragma unroll
        for (int j = 0; j < 4; j++)
            #pragma unroll
            for (int q = 0; q < 4; q++) acc[i][j][q] = 0.f;

    for (int k0 = 0; k0 < K; k0 += 16) {
        // A tile: 64 rows x 16 k  (row = tid>>1, each thread 2 float4)
        {
            int row = tid >> 1;
            const float4* src = (const float4*)(A + (long)(bm + row) * K + k0) + (tid & 1) * 2;
            float4 v0 = src[0], v1 = src[1];
            uint32_t* dst = As + row * LDT + (tid & 1) * 8;
            dst[0] = tf32_(v0.x); dst[1] = tf32_(v0.y); dst[2] = tf32_(v0.z); dst[3] = tf32_(v0.w);
            dst[4] = tf32_(v1.x); dst[5] = tf32_(v1.y); dst[6] = tf32_(v1.z); dst[7] = tf32_(v1.w);
        }
        // B tile -> Bs[n][k]
        if (TRANSB) {
            int row = tid >> 1;
            const float4* src = (const float4*)(Bw + (long)(bn + row) * K + k0) + (tid & 1) * 2;
            float4 v0 = src[0], v1 = src[1];
            uint32_t* dst = Bs + row * LDT + (tid & 1) * 8;
            dst[0] = tf32_(v0.x); dst[1] = tf32_(v0.y); dst[2] = tf32_(v0.z); dst[3] = tf32_(v0.w);
            dst[4] = tf32_(v1.x); dst[5] = tf32_(v1.y); dst[6] = tf32_(v1.z); dst[7] = tf32_(v1.w);
        } else {
            #pragma unroll
            for (int q = tid; q < 16 * 16; q += 128) {
                int k = q >> 4, f4 = q & 15;
                float4 v = *(const float4*)(Bw + (long)(k0 + k) * Nn + bn + f4 * 4);
                Bs[(f4 * 4 + 0) * LDT + k] = tf32_(v.x);
                Bs[(f4 * 4 + 1) * LDT + k] = tf32_(v.y);
                Bs[(f4 * 4 + 2) * LDT + k] = tf32_(v.z);
                Bs[(f4 * 4 + 3) * LDT + k] = tf32_(v.w);
            }
        }
        __syncthreads();
        #pragma unroll
        for (int ks = 0; ks < 16; ks += 8) {
            uint32_t af[2][4], bf[4][2];
            #pragma unroll
            for (int mi = 0; mi < 2; mi++) {
                int mr = wm + mi * 16 + (ln >> 2);
                af[mi][0] = As[mr * LDT + ks + (ln & 3)];
                af[mi][1] = As[(mr + 8) * LDT + ks + (ln & 3)];
                af[mi][2] = As[mr * LDT + ks + 4 + (ln & 3)];
                af[mi][3] = As[(mr + 8) * LDT + ks + 4 + (ln & 3)];
            }
            #pragma unroll
            for (int ni = 0; ni < 4; ni++) {
                int nr = wn + ni * 8 + (ln >> 2);
                bf[ni][0] = Bs[nr * LDT + ks + (ln & 3)];
                bf[ni][1] = Bs[nr * LDT + ks + 4 + (ln & 3)];
            }
            #pragma unroll
            for (int mi = 0; mi < 2; mi++)
                #pragma unroll
                for (int ni = 0; ni < 4; ni++)
                    mma8(acc[mi][ni], af[mi], bf[ni]);
        }
        __syncthreads();
    }
    // epilogue
    #pragma unroll
    for (int mi = 0; mi < 2; mi++) {
        #pragma unroll
        for (int ni = 0; ni < 4; ni++) {
            int m = bm + wm + mi * 16 + (ln >> 2);
            int n = bn + wn + ni * 8 + (ln & 3) * 2;
            float b0 = bias[n], b1 = bias[n + 1];
            float v0 = acc[mi][ni][0] + b0, v1 = acc[mi][ni][1] + b1;
            float v2 = acc[mi][ni][2] + b0, v3 = acc[mi][ni][3] + b1;
            if (EPI == 1) {
                v0 = (v0 > 0.f) ? v0 : expm1f(v0);
                v1 = (v1 > 0.f) ? v1 : expm1f(v1);
                v2 = (v2 > 0.f) ? v2 : expm1f(v2);
                v3 = (v3 > 0.f) ? v3 : expm1f(v3);
            }
            *(float2*)(C + (long)m * Nn + n)       = make_float2(v0, v1);
            *(float2*)(C + (long)(m + 8) * Nn + n) = make_float2(v2, v3);
        }
    }
}

// ---- fused: h = elu(wsum@W + bias_gat)  [64 blocks] ----
// ----        gh = out@W_hh^T + b_hh      [192 blocks] (independent) ----
__global__ void __launch_bounds__(128) k_h_gh(
    const float* __restrict__ W, const float* __restrict__ bias_gat,
    const float* __restrict__ W_hh, const float* __restrict__ b_hh) {
    __shared__ __align__(16) uint32_t sm[2 * 64 * LDT];
    if (blockIdx.x < 64) {
        int g = blockIdx.x;
        mma_gemm_body<HH, false, 1>(g_wsum, W, bias_gat, g_h,
                                    (g >> 2) * 64, (g & 3) * 64, sm, sm + 64 * LDT);
    } else {
        int g = blockIdx.x - 64;
        mma_gemm_body<H3, true, 0>(g_out, W_hh, b_hh, g_gh,
                                   (g / 12) * 64, (g % 12) * 64, sm, sm + 64 * LDT);
    }
}

// ---- gi = h @ W_ih^T + b_ih  [192 blocks] ----
__global__ void __launch_bounds__(128) k_gi(
    const float* __restrict__ W_ih, const float* __restrict__ b_ih) {
    __shared__ __align__(16) uint32_t sm[2 * 64 * LDT];
    int g = blockIdx.x;
    mma_gemm_body<H3, true, 0>(g_h, W_ih, b_ih, g_gi,
                               (g / 12) * 64, (g % 12) * 64, sm, sm + 64 * LDT);
}

// ---- y = out @ W_lin + b_lin  [32 blocks] ----
__global__ void __launch_bounds__(128) k_fin(
    const float* __restrict__ W_lin, const float* __restrict__ b_lin,
    float* __restrict__ C) {
    __shared__ __align__(16) uint32_t sm[2 * 64 * LDT];
    int g = blockIdx.x;
    mma_gemm_body<OUTD, false, 0>(g_out, W_lin, b_lin, C,
                                  (g >> 1) * 64, (g & 1) * 64, sm, sm + 64 * LDT);
}

// ---------------- k_gate: GRU gate combine + silu --------------------------
__global__ void k_gate() {
    int idx = blockIdx.x * 256 + threadIdx.x;      // BB*HH total
    int b = idx >> 8, j = idx & 255;
    const float* gi = g_gi + (long)b * H3;
    const float* gh = g_gh + (long)b * H3;
    float r = sigmoidf_(gi[j] + gh[j]);
    float z = sigmoidf_(gi[HH + j] + gh[HH + j]);
    float n = tanhf(gi[2 * HH + j] + r * gh[2 * HH + j]);
    float o = g_out[idx];
    float v = (1.0f - z) * n + z * o;
    g_out[idx] = v * sigmoidf_(v);                 // silu
}

// ---------------- launch --------------------------------------------------
extern "C" void kernel_launch(void* const* d_in, const int* in_sizes, int n_in,
                              void* d_out, int out_size) {
    const float* x        = (const float*)d_in[0];
    const int*   batch    = (const int*)  d_in[1];
    const float* W        = (const float*)d_in[2];
    const float* att_src  = (const float*)d_in[3];
    const float* att_dst  = (const float*)d_in[4];
    const float* bias_gat = (const float*)d_in[5];
    const float* W_ih     = (const float*)d_in[6];
    const float* W_hh     = (const float*)d_in[7];
    const float* b_ih     = (const float*)d_in[8];
    const float* b_hh     = (const float*)d_in[9];
    const float* W_lin    = (const float*)d_in[10];
    const float* b_lin    = (const float*)d_in[11];
    float* out = (float*)d_out;

    int n = in_sizes[1];   // number of nodes (batch vector length)

    k_prep<<<32, 256>>>(W, att_src, att_dst);
    k_segoff<<<(BB + 1 + 255) / 256, 256>>>(batch, n);

    // t = 0: fused pooling + attention (sweep2 rides L2)
    k_pass0_attn<<<BB, 256>>>(x);
    k_h_gh<<<64 + 192, 128>>>(W, bias_gat, W_hh, b_hh);
    k_gi<<<192, 128>>>(W_ih, b_ih);
    k_gate<<<BB * HH / 256, 256>>>();

    // t = 1: attention in reverse segment order (L2 tail reuse)
    k_attn_rev<<<BB, 256>>>(x);
    k_h_gh<<<64 + 192, 128>>>(W, bias_gat, W_hh, b_hh);
    k_gi<<<192, 128>>>(W_ih, b_ih);
    k_gate<<<BB * HH / 256, 256>>>();

    k_fin<<<32, 128>>>(W_lin, b_lin, out);         // final projection
}

// round 11
// speedup vs baseline: 1.9140x; 1.0657x over previous
#include <cuda_runtime.h>
#include <math.h>
#include <stdint.h>

// Problem constants (fixed by the dataset)
#define NN   200000
#define BB   1024
#define HH   256
#define H3   768
#define OUTD 128
#define NEG_SLOPE 0.01f

// ---------------- scratch (device globals; no allocation allowed) ----------
__device__ float g_a_src[NN];        // per-node attention source score (loop invariant)
__device__ float g_out [BB * HH];    // GRU state / pooled output
__device__ float g_wsum[BB * HH];    // per-graph alpha-weighted sum of x
__device__ float g_h   [BB * HH];    // elu(agg)
__device__ float g_gi  [BB * H3];
__device__ float g_gh  [BB * H3];
__device__ int   g_segoff[BB + 1];
__device__ float g_was[HH];          // W @ att_src
__device__ float g_wad[HH];          // W @ att_dst

// ---------------- reductions ----------------
__device__ __forceinline__ float warp_sum(float v) {
    #pragma unroll
    for (int o = 16; o; o >>= 1) v += __shfl_xor_sync(0xffffffffu, v, o);
    return v;
}
__device__ __forceinline__ float warp_max(float v) {
    #pragma unroll
    for (int o = 16; o; o >>= 1) v = fmaxf(v, __shfl_xor_sync(0xffffffffu, v, o));
    return v;
}
// 256-thread block reductions using sh[32]
__device__ __forceinline__ float block_sum(float v, float* sh) {
    int l = threadIdx.x & 31, w = threadIdx.x >> 5;
    v = warp_sum(v);
    if (l == 0) sh[w] = v;
    __syncthreads();
    if (w == 0) {
        float r = (l < 8) ? sh[l] : 0.0f;
        r = warp_sum(r);
        if (l == 0) sh[0] = r;
    }
    __syncthreads();
    float r = sh[0];
    __syncthreads();
    return r;
}
__device__ __forceinline__ float block_max(float v, float* sh) {
    int l = threadIdx.x & 31, w = threadIdx.x >> 5;
    v = warp_max(v);
    if (l == 0) sh[w] = v;
    __syncthreads();
    if (w == 0) {
        float r = (l < 8) ? sh[l] : -INFINITY;
        r = warp_max(r);
        if (l == 0) sh[0] = r;
    }
    __syncthreads();
    float r = sh[0];
    __syncthreads();
    return r;
}

__device__ __forceinline__ float sigmoidf_(float x) {
    return 1.0f / (1.0f + __expf(-x));
}

// ---------------- k_prep: w_as = W @ att_src, w_ad = W @ att_dst -----------
__global__ void k_prep(const float* __restrict__ W,
                       const float* __restrict__ att_src,
                       const float* __restrict__ att_dst) {
    int w = threadIdx.x >> 5, l = threadIdx.x & 31;
    int row = blockIdx.x * 8 + w;              // 32 blocks * 8 warps = 256 rows
    const float* Wr = W + (long)row * HH;
    float ps = 0.f, pd = 0.f;
    for (int j = l; j < HH; j += 32) {
        float v = Wr[j];
        ps += v * att_src[j];
        pd += v * att_dst[j];
    }
    ps = warp_sum(ps); pd = warp_sum(pd);
    if (l == 0) { g_was[row] = ps; g_wad[row] = pd; }
}

// ---------------- k_segoff: lower_bound per graph id -----------------------
__global__ void k_segoff(const int* __restrict__ batch, int n) {
    int j = blockIdx.x * blockDim.x + threadIdx.x;
    if (j > BB) return;
    int lo = 0, hi = n;
    while (lo < hi) {
        int mid = (lo + hi) >> 1;
        if (batch[mid] < j) lo = mid + 1; else hi = mid;
    }
    g_segoff[j] = lo;
}

// ---------------- softmax + weighted-sum core (shared by both kernels) -----
__device__ __forceinline__ void attn_core(const float* __restrict__ x,
                                          int b, int s, int e, float adst,
                                          float* red, float* shr) {
    int tid = threadIdx.x, w = tid >> 5, l = tid & 31;

    // single pass over a_src: per-thread online (max, sum)
    float m = -INFINITY, d = 0.f;
    for (int r = s + tid; r < e; r += 256) {
        float ev = g_a_src[r] + adst;
        ev = ev > 0.f ? ev : NEG_SLOPE * ev;
        float mn = fmaxf(m, ev);
        d = d * __expf(m - mn) + __expf(ev - mn);
        m = mn;
    }
    float M = block_max(m, shr);
    float dd = (d > 0.f) ? d * __expf(m - M) : 0.f;
    float D = block_sum(dd, shr);
    float inv = (e > s) ? 1.0f / D : 0.0f;

    // weighted sum of x rows (float4, 2x unroll)
    float4 acc0 = make_float4(0.f, 0.f, 0.f, 0.f);
    float4 acc1 = make_float4(0.f, 0.f, 0.f, 0.f);
    int r = s + w;
    for (; r + 8 < e; r += 16) {
        float e0 = g_a_src[r] + adst;
        float e1 = g_a_src[r + 8] + adst;
        e0 = e0 > 0.f ? e0 : NEG_SLOPE * e0;
        e1 = e1 > 0.f ? e1 : NEG_SLOPE * e1;
        float al0 = __expf(e0 - M) * inv;
        float al1 = __expf(e1 - M) * inv;
        const float4* x0 = (const float4*)(x + (long)r * HH);
        const float4* x1 = (const float4*)(x + (long)(r + 8) * HH);
        float4 a0 = x0[l], c0 = x0[l + 32];
        float4 a1 = x1[l], c1 = x1[l + 32];
        acc0.x += al0 * a0.x + al1 * a1.x; acc0.y += al0 * a0.y + al1 * a1.y;
        acc0.z += al0 * a0.z + al1 * a1.z; acc0.w += al0 * a0.w + al1 * a1.w;
        acc1.x += al0 * c0.x + al1 * c1.x; acc1.y += al0 * c0.y + al1 * c1.y;
        acc1.z += al0 * c0.z + al1 * c1.z; acc1.w += al0 * c0.w + al1 * c1.w;
    }
    if (r < e) {
        float e0 = g_a_src[r] + adst;
        e0 = e0 > 0.f ? e0 : NEG_SLOPE * e0;
        float al0 = __expf(e0 - M) * inv;
        const float4* x0 = (const float4*)(x + (long)r * HH);
        float4 a0 = x0[l], c0 = x0[l + 32];
        acc0.x += al0 * a0.x; acc0.y += al0 * a0.y;
        acc0.z += al0 * a0.z; acc0.w += al0 * a0.w;
        acc1.x += al0 * c0.x; acc1.y += al0 * c0.y;
        acc1.z += al0 * c0.z; acc1.w += al0 * c0.w;
    }
    float4* redw = (float4*)(red + w * HH);
    redw[l] = acc0;
    redw[l + 32] = acc1;
    __syncthreads();
    float sum = 0.f;
    #pragma unroll
    for (int ww = 0; ww < 8; ww++) sum += red[ww * HH + tid];
    g_wsum[(long)b * HH + tid] = sum;
}

// ---------------- k_pass0_attn: fused pool + t=0 attention -----------------
__global__ void __launch_bounds__(256) k_pass0_attn(const float* __restrict__ x) {
    __shared__ __align__(16) float red[8 * HH];   // [8 warps][256 cols]
    __shared__ float shr[32];
    int b = blockIdx.x;
    int tid = threadIdx.x, w = tid >> 5, l = tid & 31;
    int s = g_segoff[b], e = g_segoff[b + 1];

    const float4* was4 = (const float4*)g_was;
    float4 wa = was4[l], wb = was4[l + 32];

    float4 acc0 = make_float4(0.f, 0.f, 0.f, 0.f);
    float4 acc1 = make_float4(0.f, 0.f, 0.f, 0.f);

    int r = s + w;
    for (; r + 8 < e; r += 16) {
        const float4* x0 = (const float4*)(x + (long)r * HH);
        const float4* x1 = (const float4*)(x + (long)(r + 8) * HH);
        float4 a0 = x0[l], c0 = x0[l + 32];
        float4 a1 = x1[l], c1 = x1[l + 32];
        acc0.x += a0.x + a1.x; acc0.y += a0.y + a1.y;
        acc0.z += a0.z + a1.z; acc0.w += a0.w + a1.w;
        acc1.x += c0.x + c1.x; acc1.y += c0.y + c1.y;
        acc1.z += c0.z + c1.z; acc1.w += c0.w + c1.w;
        float p0 = a0.x * wa.x + a0.y * wa.y + a0.z * wa.z + a0.w * wa.w
                 + c0.x * wb.x + c0.y * wb.y + c0.z * wb.z + c0.w * wb.w;
        float p1 = a1.x * wa.x + a1.y * wa.y + a1.z * wa.z + a1.w * wa.w
                 + c1.x * wb.x + c1.y * wb.y + c1.z * wb.z + c1.w * wb.w;
        p0 = warp_sum(p0);
        p1 = warp_sum(p1);
        if (l == 0) { g_a_src[r] = p0; g_a_src[r + 8] = p1; }
    }
    if (r < e) {
        const float4* x0 = (const float4*)(x + (long)r * HH);
        float4 a0 = x0[l], c0 = x0[l + 32];
        acc0.x += a0.x; acc0.y += a0.y; acc0.z += a0.z; acc0.w += a0.w;
        acc1.x += c0.x; acc1.y += c0.y; acc1.z += c0.z; acc1.w += c0.w;
        float p0 = a0.x * wa.x + a0.y * wa.y + a0.z * wa.z + a0.w * wa.w
                 + c0.x * wb.x + c0.y * wb.y + c0.z * wb.z + c0.w * wb.w;
        p0 = warp_sum(p0);
        if (l == 0) g_a_src[r] = p0;
    }
    float4* redw = (float4*)(red + w * HH);
    redw[l] = acc0;
    redw[l + 32] = acc1;
    __syncthreads();
    float sum = 0.f;
    #pragma unroll
    for (int ww = 0; ww < 8; ww++) sum += red[ww * HH + tid];
    g_out[(long)b * HH + tid] = sum;

    // adst from the locally computed pooled sum (no extra global pass)
    float adst = block_sum(sum * g_wad[tid], shr);

    attn_core(x, b, s, e, adst, red, shr);
}

// ---------------- k_attn_rev: t=1 attention, reversed segment order --------
__global__ void __launch_bounds__(256, 6) k_attn_rev(const float* __restrict__ x) {
    __shared__ __align__(16) float red[8 * HH];
    __shared__ float shr[32];
    int b = (BB - 1) - blockIdx.x;
    int tid = threadIdx.x;
    int s = g_segoff[b], e = g_segoff[b + 1];

    float adst = block_sum(g_out[(long)b * HH + tid] * g_wad[tid], shr);
    attn_core(x, b, s, e, adst, red, shr);
}

// ================= tf32 tensor-core GEMM (2-stage pipelined) ==============
// C[1024, Nn] = A[1024, 256] * B (+bias, epilogue)
// BM=128, BN=64, BK=16; 256 threads = 8 warps (4x2), warp tile 32x32.
// TRANSB=true : B stored [Nn, 256] row-major (op = A @ B^T)
// TRANSB=false: B stored [256, Nn] row-major
#define LDT   20              // padded smem row stride (conflict-free)
#define ASTR  (128 * LDT)     // per-stage A words
#define BSTR  (64 * LDT)      // per-stage B words

__device__ __forceinline__ uint32_t tf32_(float x) {
    uint32_t r;
    asm("cvt.rna.tf32.f32 %0, %1;" : "=r"(r) : "f"(x));
    return r;
}
__device__ __forceinline__ void mma8(float* c, const uint32_t* a, const uint32_t* b) {
    asm("mma.sync.aligned.m16n8k8.row.col.f32.tf32.tf32.f32 "
        "{%0,%1,%2,%3}, {%4,%5,%6,%7}, {%8,%9}, {%0,%1,%2,%3};"
        : "+f"(c[0]), "+f"(c[1]), "+f"(c[2]), "+f"(c[3])
        : "r"(a[0]), "r"(a[1]), "r"(a[2]), "r"(a[3]), "r"(b[0]), "r"(b[1]));
}

template <int Nn, bool TRANSB, int EPI>
__device__ __forceinline__ void mma_gemm_body(
    const float* __restrict__ A, const float* __restrict__ Bw,
    const float* __restrict__ bias, float* __restrict__ C,
    int bm, int bn, uint32_t* As, uint32_t* Bs) {

    const int K = HH;                 // 256, 16 K-chunks of 16
    int tid = threadIdx.x, ln = tid & 31, w = tid >> 5;
    int wm = (w >> 1) * 32, wn = (w & 1) * 32;

    float acc[2][4][4];
    #pragma unroll
    for (int i = 0; i < 2; i++)
        #pragma unroll
        for (int j = 0; j < 4; j++)
            #pragma unroll
            for (int q = 0; q < 4; q++) acc[i][j][q] = 0.f;

    // per-thread LDG staging registers
    float4 ra0, ra1, rb;
    int arow = tid >> 1, aoff = (tid & 1) * 8;          // A: 128 rows x 16k
    // B (TRANSB): 64 rows x 16k ; (!TRANSB): transpose-on-store
    int brow = tid >> 2, bkf = (tid & 3) * 4;           // TRANSB mapping
    int tk = tid >> 4, tf4 = tid & 15;                  // !TRANSB mapping

    #define LDG_TILE(k0)                                                          \
        {                                                                         \
            const float4* sa = (const float4*)(A + (long)(bm + arow) * K + (k0)) +\
                               (tid & 1) * 2;                                     \
            ra0 = sa[0]; ra1 = sa[1];                                             \
            if (TRANSB) rb = *(const float4*)(Bw + (long)(bn + brow) * K + (k0) + bkf); \
            else        rb = *(const float4*)(Bw + (long)((k0) + tk) * Nn + bn + tf4 * 4); \
        }

    #define STS_TILE(st)                                                          \
        {                                                                         \
            uint32_t* da = As + (st) * ASTR + arow * LDT + aoff;                  \
            da[0] = tf32_(ra0.x); da[1] = tf32_(ra0.y);                           \
            da[2] = tf32_(ra0.z); da[3] = tf32_(ra0.w);                           \
            da[4] = tf32_(ra1.x); da[5] = tf32_(ra1.y);                           \
            da[6] = tf32_(ra1.z); da[7] = tf32_(ra1.w);                           \
            uint32_t* db = Bs + (st) * BSTR;                                      \
            if (TRANSB) {                                                         \
                db += brow * LDT + bkf;                                           \
                db[0] = tf32_(rb.x); db[1] = tf32_(rb.y);                         \
                db[2] = tf32_(rb.z); db[3] = tf32_(rb.w);                         \
            } else {                                                              \
                db[(tf4 * 4 + 0) * LDT + tk] = tf32_(rb.x);                       \
                db[(tf4 * 4 + 1) * LDT + tk] = tf32_(rb.y);                       \
                db[(tf4 * 4 + 2) * LDT + tk] = tf32_(rb.z);                       \
                db[(tf4 * 4 + 3) * LDT + tk] = tf32_(rb.w);                       \
            }                                                                     \
        }

    // prologue
    LDG_TILE(0);
    STS_TILE(0);
    __syncthreads();

    #pragma unroll 2
    for (int ks = 0; ks < K / 16; ks++) {
        int cur = ks & 1;
        if (ks + 1 < K / 16) LDG_TILE((ks + 1) * 16);   // overlap with mma below
        const uint32_t* Ac = As + cur * ASTR;
        const uint32_t* Bc = Bs + cur * BSTR;
        #pragma unroll
        for (int k8 = 0; k8 < 16; k8 += 8) {
            uint32_t af[2][4], bf[4][2];
            #pragma unroll
            for (int mi = 0; mi < 2; mi++) {
                int mr = wm + mi * 16 + (ln >> 2);
                af[mi][0] = Ac[mr * LDT + k8 + (ln & 3)];
                af[mi][1] = Ac[(mr + 8) * LDT + k8 + (ln & 3)];
                af[mi][2] = Ac[mr * LDT + k8 + 4 + (ln & 3)];
                af[mi][3] = Ac[(mr + 8) * LDT + k8 + 4 + (ln & 3)];
            }
            #pragma unroll
            for (int ni = 0; ni < 4; ni++) {
                int nr = wn + ni * 8 + (ln >> 2);
                bf[ni][0] = Bc[nr * LDT + k8 + (ln & 3)];
                bf[ni][1] = Bc[nr * LDT + k8 + 4 + (ln & 3)];
            }
            #pragma unroll
            for (int mi = 0; mi < 2; mi++)
                #pragma unroll
                for (int ni = 0; ni < 4; ni++)
                    mma8(acc[mi][ni], af[mi], bf[ni]);
        }
        __syncthreads();
        if (ks + 1 < K / 16) {
            STS_TILE(1 - cur);
            __syncthreads();
        }
    }
    #undef LDG_TILE
    #undef STS_TILE

    // epilogue
    #pragma unroll
    for (int mi = 0; mi < 2; mi++) {
        #pragma unroll
        for (int ni = 0; ni < 4; ni++) {
            int m = bm + wm + mi * 16 + (ln >> 2);
            int n = bn + wn + ni * 8 + (ln & 3) * 2;
            float b0 = bias[n], b1 = bias[n + 1];
            float v0 = acc[mi][ni][0] + b0, v1 = acc[mi][ni][1] + b1;
            float v2 = acc[mi][ni][2] + b0, v3 = acc[mi][ni][3] + b1;
            if (EPI == 1) {
                v0 = (v0 > 0.f) ? v0 : expm1f(v0);
                v1 = (v1 > 0.f) ? v1 : expm1f(v1);
                v2 = (v2 > 0.f) ? v2 : expm1f(v2);
                v3 = (v3 > 0.f) ? v3 : expm1f(v3);
            }
            *(float2*)(C + (long)m * Nn + n)       = make_float2(v0, v1);
            *(float2*)(C + (long)(m + 8) * Nn + n) = make_float2(v2, v3);
        }
    }
}

// smem: 2 stages A (128x20) + 2 stages B (64x20) = 7680 u32 = 30 KB
#define GEMM_SMEM (2 * ASTR + 2 * BSTR)

// ---- fused: h = elu(wsum@W + bias_gat)  [32 blocks: 8m x 4n] ----
// ----        gh = out@W_hh^T + b_hh      [96 blocks: 8m x 12n] ----
__global__ void __launch_bounds__(256) k_h_gh(
    const float* __restrict__ W, const float* __restrict__ bias_gat,
    const float* __restrict__ W_hh, const float* __restrict__ b_hh) {
    __shared__ __align__(16) uint32_t sm[GEMM_SMEM];
    if (blockIdx.x < 32) {
        int g = blockIdx.x;
        mma_gemm_body<HH, false, 1>(g_wsum, W, bias_gat, g_h,
                                    (g >> 2) * 128, (g & 3) * 64, sm, sm + 2 * ASTR);
    } else {
        int g = blockIdx.x - 32;
        mma_gemm_body<H3, true, 0>(g_out, W_hh, b_hh, g_gh,
                                   (g / 12) * 128, (g % 12) * 64, sm, sm + 2 * ASTR);
    }
}

// ---- gi = h @ W_ih^T + b_ih  [96 blocks] ----
__global__ void __launch_bounds__(256) k_gi(
    const float* __restrict__ W_ih, const float* __restrict__ b_ih) {
    __shared__ __align__(16) uint32_t sm[GEMM_SMEM];
    int g = blockIdx.x;
    mma_gemm_body<H3, true, 0>(g_h, W_ih, b_ih, g_gi,
                               (g / 12) * 128, (g % 12) * 64, sm, sm + 2 * ASTR);
}

// ---- y = out @ W_lin + b_lin  [16 blocks] ----
__global__ void __launch_bounds__(256) k_fin(
    const float* __restrict__ W_lin, const float* __restrict__ b_lin,
    float* __restrict__ C) {
    __shared__ __align__(16) uint32_t sm[GEMM_SMEM];
    int g = blockIdx.x;
    mma_gemm_body<OUTD, false, 0>(g_out, W_lin, b_lin, C,
                                  (g >> 1) * 128, (g & 1) * 64, sm, sm + 2 * ASTR);
}

// ---------------- k_gate: GRU gate combine + silu --------------------------
__global__ void k_gate() {
    int idx = blockIdx.x * 256 + threadIdx.x;      // BB*HH total
    int b = idx >> 8, j = idx & 255;
    const float* gi = g_gi + (long)b * H3;
    const float* gh = g_gh + (long)b * H3;
    float r = sigmoidf_(gi[j] + gh[j]);
    float z = sigmoidf_(gi[HH + j] + gh[HH + j]);
    float n = tanhf(gi[2 * HH + j] + r * gh[2 * HH + j]);
    float o = g_out[idx];
    float v = (1.0f - z) * n + z * o;
    g_out[idx] = v * sigmoidf_(v);                 // silu
}

// ---------------- launch --------------------------------------------------
extern "C" void kernel_launch(void* const* d_in, const int* in_sizes, int n_in,
                              void* d_out, int out_size) {
    const float* x        = (const float*)d_in[0];
    const int*   batch    = (const int*)  d_in[1];
    const float* W        = (const float*)d_in[2];
    const float* att_src  = (const float*)d_in[3];
    const float* att_dst  = (const float*)d_in[4];
    const float* bias_gat = (const float*)d_in[5];
    const float* W_ih     = (const float*)d_in[6];
    const float* W_hh     = (const float*)d_in[7];
    const float* b_ih     = (const float*)d_in[8];
    const float* b_hh     = (const float*)d_in[9];
    const float* W_lin    = (const float*)d_in[10];
    const float* b_lin    = (const float*)d_in[11];
    float* out = (float*)d_out;

    int n = in_sizes[1];   // number of nodes (batch vector length)

    k_prep<<<32, 256>>>(W, att_src, att_dst);
    k_segoff<<<(BB + 1 + 255) / 256, 256>>>(batch, n);

    // t = 0: fused pooling + attention (sweep2 rides L2)
    k_pass0_attn<<<BB, 256>>>(x);
    k_h_gh<<<32 + 96, 256>>>(W, bias_gat, W_hh, b_hh);
    k_gi<<<96, 256>>>(W_ih, b_ih);
    k_gate<<<BB * HH / 256, 256>>>();

    // t = 1: attention in reverse segment order (L2 tail reuse)
    k_attn_rev<<<BB, 256>>>(x);
    k_h_gh<<<32 + 96, 256>>>(W, bias_gat, W_hh, b_hh);
    k_gi<<<96, 256>>>(W_ih, b_ih);
    k_gate<<<BB * HH / 256, 256>>>();

    k_fin<<<16, 256>>>(W_lin, b_lin, out);         // final projection
}

// round 14
// speedup vs baseline: 2.1860x; 1.1422x over previous
#include <cuda_runtime.h>
#include <math.h>
#include <stdint.h>

// Problem constants (fixed by the dataset)
#define NN   200000
#define BB   1024
#define HH   256
#define H3   768
#define OUTD 128
#define NEG_SLOPE 0.01f

// ---------------- scratch (device globals; no allocation allowed) ----------
__device__ float g_a_src[NN];
__device__ float g_out [BB * HH];
__device__ float g_wsum[BB * HH];
__device__ float g_h   [BB * HH];
__device__ float g_gi  [BB * H3];
__device__ float g_gh  [BB * H3];
__device__ int   g_segoff[BB + 1];
__device__ float g_was[HH];
__device__ float g_wad[HH];

// ---------------- reductions ----------------
__device__ __forceinline__ float warp_sum(float v) {
    #pragma unroll
    for (int o = 16; o; o >>= 1) v += __shfl_xor_sync(0xffffffffu, v, o);
    return v;
}
__device__ __forceinline__ float warp_max(float v) {
    #pragma unroll
    for (int o = 16; o; o >>= 1) v = fmaxf(v, __shfl_xor_sync(0xffffffffu, v, o));
    return v;
}
__device__ __forceinline__ float block_sum(float v, float* sh) {
    int l = threadIdx.x & 31, w = threadIdx.x >> 5;
    v = warp_sum(v);
    if (l == 0) sh[w] = v;
    __syncthreads();
    if (w == 0) {
        float r = (l < 8) ? sh[l] : 0.0f;
        r = warp_sum(r);
        if (l == 0) sh[0] = r;
    }
    __syncthreads();
    float r = sh[0];
    __syncthreads();
    return r;
}
__device__ __forceinline__ float block_max(float v, float* sh) {
    int l = threadIdx.x & 31, w = threadIdx.x >> 5;
    v = warp_max(v);
    if (l == 0) sh[w] = v;
    __syncthreads();
    if (w == 0) {
        float r = (l < 8) ? sh[l] : -INFINITY;
        r = warp_max(r);
        if (l == 0) sh[0] = r;
    }
    __syncthreads();
    float r = sh[0];
    __syncthreads();
    return r;
}

__device__ __forceinline__ float sigmoidf_(float x) {
    return 1.0f / (1.0f + __expf(-x));
}

// ---------------- k_prep: w_as = W @ att_src, w_ad = W @ att_dst -----------
__global__ void k_prep(const float* __restrict__ W,
                       const float* __restrict__ att_src,
                       const float* __restrict__ att_dst) {
    int w = threadIdx.x >> 5, l = threadIdx.x & 31;
    int row = blockIdx.x * 8 + w;
    const float* Wr = W + (long)row * HH;
    float ps = 0.f, pd = 0.f;
    for (int j = l; j < HH; j += 32) {
        float v = Wr[j];
        ps += v * att_src[j];
        pd += v * att_dst[j];
    }
    ps = warp_sum(ps); pd = warp_sum(pd);
    if (l == 0) { g_was[row] = ps; g_wad[row] = pd; }
}

// ---------------- k_segoff: lower_bound per graph id -----------------------
__global__ void k_segoff(const int* __restrict__ batch, int n) {
    int j = blockIdx.x * blockDim.x + threadIdx.x;
    if (j > BB) return;
    int lo = 0, hi = n;
    while (lo < hi) {
        int mid = (lo + hi) >> 1;
        if (batch[mid] < j) lo = mid + 1; else hi = mid;
    }
    g_segoff[j] = lo;
}

// ---------------- softmax + weighted-sum core ------------------------------
__device__ __forceinline__ void attn_core(const float* __restrict__ x,
                                          int b, int s, int e, float adst,
                                          float* red, float* shr) {
    int tid = threadIdx.x, w = tid >> 5, l = tid & 31;

    float m = -INFINITY, d = 0.f;
    for (int r = s + tid; r < e; r += 256) {
        float ev = g_a_src[r] + adst;
        ev = ev > 0.f ? ev : NEG_SLOPE * ev;
        float mn = fmaxf(m, ev);
        d = d * __expf(m - mn) + __expf(ev - mn);
        m = mn;
    }
    float M = block_max(m, shr);
    float dd = (d > 0.f) ? d * __expf(m - M) : 0.f;
    float D = block_sum(dd, shr);
    float inv = (e > s) ? 1.0f / D : 0.0f;

    float4 acc0 = make_float4(0.f, 0.f, 0.f, 0.f);
    float4 acc1 = make_float4(0.f, 0.f, 0.f, 0.f);
    int r = s + w;
    for (; r + 8 < e; r += 16) {
        float e0 = g_a_src[r] + adst;
        float e1 = g_a_src[r + 8] + adst;
        e0 = e0 > 0.f ? e0 : NEG_SLOPE * e0;
        e1 = e1 > 0.f ? e1 : NEG_SLOPE * e1;
        float al0 = __expf(e0 - M) * inv;
        float al1 = __expf(e1 - M) * inv;
        const float4* x0 = (const float4*)(x + (long)r * HH);
        const float4* x1 = (const float4*)(x + (long)(r + 8) * HH);
        float4 a0 = x0[l], c0 = x0[l + 32];
        float4 a1 = x1[l], c1 = x1[l + 32];
        acc0.x += al0 * a0.x + al1 * a1.x; acc0.y += al0 * a0.y + al1 * a1.y;
        acc0.z += al0 * a0.z + al1 * a1.z; acc0.w += al0 * a0.w + al1 * a1.w;
        acc1.x += al0 * c0.x + al1 * c1.x; acc1.y += al0 * c0.y + al1 * c1.y;
        acc1.z += al0 * c0.z + al1 * c1.z; acc1.w += al0 * c0.w + al1 * c1.w;
    }
    if (r < e) {
        float e0 = g_a_src[r] + adst;
        e0 = e0 > 0.f ? e0 : NEG_SLOPE * e0;
        float al0 = __expf(e0 - M) * inv;
        const float4* x0 = (const float4*)(x + (long)r * HH);
        float4 a0 = x0[l], c0 = x0[l + 32];
        acc0.x += al0 * a0.x; acc0.y += al0 * a0.y;
        acc0.z += al0 * a0.z; acc0.w += al0 * a0.w;
        acc1.x += al0 * c0.x; acc1.y += al0 * c0.y;
        acc1.z += al0 * c0.z; acc1.w += al0 * c0.w;
    }
    float4* redw = (float4*)(red + w * HH);
    redw[l] = acc0;
    redw[l + 32] = acc1;
    __syncthreads();
    float sum = 0.f;
    #pragma unroll
    for (int ww = 0; ww < 8; ww++) sum += red[ww * HH + tid];
    g_wsum[(long)b * HH + tid] = sum;
}

// ---------------- k_pass0_attn: fused pool + t=0 attention -----------------
__global__ void __launch_bounds__(256) k_pass0_attn(const float* __restrict__ x) {
    __shared__ __align__(16) float red[8 * HH];
    __shared__ float shr[32];
    int b = blockIdx.x;
    int tid = threadIdx.x, w = tid >> 5, l = tid & 31;
    int s = g_segoff[b], e = g_segoff[b + 1];

    const float4* was4 = (const float4*)g_was;
    float4 wa = was4[l], wb = was4[l + 32];

    float4 acc0 = make_float4(0.f, 0.f, 0.f, 0.f);
    float4 acc1 = make_float4(0.f, 0.f, 0.f, 0.f);

    int r = s + w;
    for (; r + 8 < e; r += 16) {
        const float4* x0 = (const float4*)(x + (long)r * HH);
        const float4* x1 = (const float4*)(x + (long)(r + 8) * HH);
        float4 a0 = x0[l], c0 = x0[l + 32];
        float4 a1 = x1[l], c1 = x1[l + 32];
        acc0.x += a0.x + a1.x; acc0.y += a0.y + a1.y;
        acc0.z += a0.z + a1.z; acc0.w += a0.w + a1.w;
        acc1.x += c0.x + c1.x; acc1.y += c0.y + c1.y;
        acc1.z += c0.z + c1.z; acc1.w += c0.w + c1.w;
        float p0 = a0.x * wa.x + a0.y * wa.y + a0.z * wa.z + a0.w * wa.w
                 + c0.x * wb.x + c0.y * wb.y + c0.z * wb.z + c0.w * wb.w;
        float p1 = a1.x * wa.x + a1.y * wa.y + a1.z * wa.z + a1.w * wa.w
                 + c1.x * wb.x + c1.y * wb.y + c1.z * wb.z + c1.w * wb.w;
        p0 = warp_sum(p0);
        p1 = warp_sum(p1);
        if (l == 0) { g_a_src[r] = p0; g_a_src[r + 8] = p1; }
    }
    if (r < e) {
        const float4* x0 = (const float4*)(x + (long)r * HH);
        float4 a0 = x0[l], c0 = x0[l + 32];
        acc0.x += a0.x; acc0.y += a0.y; acc0.z += a0.z; acc0.w += a0.w;
        acc1.x += c0.x; acc1.y += c0.y; acc1.z += c0.z; acc1.w += c0.w;
        float p0 = a0.x * wa.x + a0.y * wa.y + a0.z * wa.z + a0.w * wa.w
                 + c0.x * wb.x + c0.y * wb.y + c0.z * wb.z + c0.w * wb.w;
        p0 = warp_sum(p0);
        if (l == 0) g_a_src[r] = p0;
    }
    float4* redw = (float4*)(red + w * HH);
    redw[l] = acc0;
    redw[l + 32] = acc1;
    __syncthreads();
    float sum = 0.f;
    #pragma unroll
    for (int ww = 0; ww < 8; ww++) sum += red[ww * HH + tid];
    g_out[(long)b * HH + tid] = sum;

    float adst = block_sum(sum * g_wad[tid], shr);
    attn_core(x, b, s, e, adst, red, shr);
}

// ---------------- k_attn_rev: t=1 attention, reversed segment order --------
__global__ void __launch_bounds__(256, 6) k_attn_rev(const float* __restrict__ x) {
    __shared__ __align__(16) float red[8 * HH];
    __shared__ float shr[32];
    int b = (BB - 1) - blockIdx.x;
    int tid = threadIdx.x;
    int s = g_segoff[b], e = g_segoff[b + 1];

    float adst = block_sum(g_out[(long)b * HH + tid] * g_wad[tid], shr);
    attn_core(x, b, s, e, adst, red, shr);
}

// ================= tf32 tensor-core GEMM (3-stage cp.async) ===============
// C[1024, Nn] = A[1024, 256] * B (+bias, epilogue)
// BM=128, BN=64, BK=16; 256 threads = 8 warps (4x2), warp tile 32x32.
// smem holds raw fp32 (cp.async), tf32 conversion at fragment load.
// TRANSB=true : B stored [Nn, 256] row-major (op = A @ B^T), smem [n][k]
// TRANSB=false: B stored [256, Nn] row-major,               smem [k][n]
#define GK    16
#define LDA_  20               // A smem row stride ([m][k] + pad)
#define LDBT  20               // B smem stride, TRANSB layout [n][k]
#define LDBN  72               // B smem stride, !TRANSB layout [k][n] (72%32=8)
#define ASTG  (128 * LDA_)     // 2560 floats / stage
#define BSTG  (64 * LDBT)      // 1280 floats / stage (>= 16*LDBN = 1152)
#define STG   (ASTG + BSTG)    // 3840 floats / stage; 3 stages = 45 KB

__device__ __forceinline__ uint32_t tf32_(float x) {
    uint32_t r;
    asm("cvt.rna.tf32.f32 %0, %1;" : "=r"(r) : "f"(x));
    return r;
}
__device__ __forceinline__ void mma8(float* c, const uint32_t* a, const uint32_t* b) {
    asm("mma.sync.aligned.m16n8k8.row.col.f32.tf32.tf32.f32 "
        "{%0,%1,%2,%3}, {%4,%5,%6,%7}, {%8,%9}, {%0,%1,%2,%3};"
        : "+f"(c[0]), "+f"(c[1]), "+f"(c[2]), "+f"(c[3])
        : "r"(a[0]), "r"(a[1]), "r"(a[2]), "r"(a[3]), "r"(b[0]), "r"(b[1]));
}
__device__ __forceinline__ void cp16(float* dst, const float* src) {
    uint32_t da = (uint32_t)__cvta_generic_to_shared(dst);
    asm volatile("cp.async.cg.shared.global [%0], [%1], 16;" :: "r"(da), "l"(src));
}
__device__ __forceinline__ void cp_commit() {
    asm volatile("cp.async.commit_group;");
}
template <int N> __device__ __forceinline__ void cp_wait() {
    asm volatile("cp.async.wait_group %0;" :: "n"(N));
}

// Issue one BK=16 stage: A tile 128x16, B tile (64x16 | 16x64)
template <int Nn, bool TRANSB>
__device__ __forceinline__ void issue_stage(
    float* Sa, float* Sb, const float* __restrict__ A, const float* __restrict__ Bw,
    int bm, int bn, int k0) {
    const int K = HH;
    int tid = threadIdx.x;
    #pragma unroll
    for (int q = 0; q < 2; q++) {                 // A: 512 16B-chunks
        int c = tid + q * 256, row = c >> 2, c4 = c & 3;
        cp16(Sa + row * LDA_ + c4 * 4, A + (long)(bm + row) * K + k0 + c4 * 4);
    }
    if (TRANSB) {                                  // B: [n][k], 256 chunks
        int nrow = tid >> 2, c4 = tid & 3;
        cp16(Sb + nrow * LDBT + c4 * 4, Bw + (long)(bn + nrow) * K + k0 + c4 * 4);
    } else {                                       // B: [k][n], 256 chunks
        int k = tid >> 4, c4 = tid & 15;
        cp16(Sb + k * LDBN + c4 * 4, Bw + (long)(k0 + k) * Nn + bn + c4 * 4);
    }
    cp_commit();
}

template <int Nn, bool TRANSB>
__device__ __forceinline__ void consume_stage(
    const float* Ac, const float* Bc, float acc[2][4][4], int ln, int wm, int wn) {
    #pragma unroll
    for (int k8 = 0; k8 < GK; k8 += 8) {
        uint32_t af[2][4], bf[4][2];
        #pragma unroll
        for (int mi = 0; mi < 2; mi++) {
            int mr = wm + mi * 16 + (ln >> 2);
            af[mi][0] = tf32_(Ac[mr * LDA_ + k8 + (ln & 3)]);
            af[mi][1] = tf32_(Ac[(mr + 8) * LDA_ + k8 + (ln & 3)]);
            af[mi][2] = tf32_(Ac[mr * LDA_ + k8 + 4 + (ln & 3)]);
            af[mi][3] = tf32_(Ac[(mr + 8) * LDA_ + k8 + 4 + (ln & 3)]);
        }
        #pragma unroll
        for (int ni = 0; ni < 4; ni++) {
            int nr = wn + ni * 8 + (ln >> 2);
            if (TRANSB) {
                bf[ni][0] = tf32_(Bc[nr * LDBT + k8 + (ln & 3)]);
                bf[ni][1] = tf32_(Bc[nr * LDBT + k8 + 4 + (ln & 3)]);
            } else {
                bf[ni][0] = tf32_(Bc[(k8 + (ln & 3)) * LDBN + nr]);
                bf[ni][1] = tf32_(Bc[(k8 + 4 + (ln & 3)) * LDBN + nr]);
            }
        }
        #pragma unroll
        for (int mi = 0; mi < 2; mi++)
            #pragma unroll
            for (int ni = 0; ni < 4; ni++)
                mma8(acc[mi][ni], af[mi], bf[ni]);
    }
}

template <int Nn, bool TRANSB, int EPI>
__device__ __forceinline__ void mma_gemm_body(
    const float* __restrict__ A, const float* __restrict__ Bw,
    const float* __restrict__ bias, float* __restrict__ C,
    int bm, int bn, float* sm) {

    const int K = HH, NIT = K / GK;      // 16 iterations
    int tid = threadIdx.x, ln = tid & 31, w = tid >> 5;
    int wm = (w >> 1) * 32, wn = (w & 1) * 32;

    float acc[2][4][4];
    #pragma unroll
    for (int i = 0; i < 2; i++)
        #pragma unroll
        for (int j = 0; j < 4; j++)
            #pragma unroll
            for (int q = 0; q < 4; q++) acc[i][j][q] = 0.f;

    // prologue: stages 0, 1 in flight
    issue_stage<Nn, TRANSB>(sm, sm + ASTG, A, Bw, bm, bn, 0);
    issue_stage<Nn, TRANSB>(sm + STG, sm + STG + ASTG, A, Bw, bm, bn, GK);

    #pragma unroll
    for (int i = 0; i < NIT - 1; i++) {
        cp_wait<1>();            // stage i landed
        __syncthreads();         // all warps past iter i-1 reads
        if (i + 2 < NIT) {
            int st = (i + 2) % 3;
            issue_stage<Nn, TRANSB>(sm + st * STG, sm + st * STG + ASTG,
                                    A, Bw, bm, bn, (i + 2) * GK);
        }
        int cs = i % 3;
        consume_stage<Nn, TRANSB>(sm + cs * STG, sm + cs * STG + ASTG,
                                  acc, ln, wm, wn);
    }
    cp_wait<0>();
    __syncthreads();
    {
        int cs = (NIT - 1) % 3;
        consume_stage<Nn, TRANSB>(sm + cs * STG, sm + cs * STG + ASTG,
                                  acc, ln, wm, wn);
    }

    // epilogue
    #pragma unroll
    for (int mi = 0; mi < 2; mi++) {
        #pragma unroll
        for (int ni = 0; ni < 4; ni++) {
            int m = bm + wm + mi * 16 + (ln >> 2);
            int n = bn + wn + ni * 8 + (ln & 3) * 2;
            float b0 = bias[n], b1 = bias[n + 1];
            float v0 = acc[mi][ni][0] + b0, v1 = acc[mi][ni][1] + b1;
            float v2 = acc[mi][ni][2] + b0, v3 = acc[mi][ni][3] + b1;
            if (EPI == 1) {
                v0 = (v0 > 0.f) ? v0 : expm1f(v0);
                v1 = (v1 > 0.f) ? v1 : expm1f(v1);
                v2 = (v2 > 0.f) ? v2 : expm1f(v2);
                v3 = (v3 > 0.f) ? v3 : expm1f(v3);
            }
            *(float2*)(C + (long)m * Nn + n)       = make_float2(v0, v1);
            *(float2*)(C + (long)(m + 8) * Nn + n) = make_float2(v2, v3);
        }
    }
}

#define GEMM_SMEM (3 * STG)   // 11520 floats = 45 KB

// ---- fused: h = elu(wsum@W + bias_gat)  [32 blocks: 8m x 4n] ----
// ----        gh = out@W_hh^T + b_hh      [96 blocks: 8m x 12n] ----
__global__ void __launch_bounds__(256) k_h_gh(
    const float* __restrict__ W, const float* __restrict__ bias_gat,
    const float* __restrict__ W_hh, const float* __restrict__ b_hh) {
    __shared__ __align__(16) float sm[GEMM_SMEM];
    if (blockIdx.x < 32) {
        int g = blockIdx.x;
        mma_gemm_body<HH, false, 1>(g_wsum, W, bias_gat, g_h,
                                    (g >> 2) * 128, (g & 3) * 64, sm);
    } else {
        int g = blockIdx.x - 32;
        mma_gemm_body<H3, true, 0>(g_out, W_hh, b_hh, g_gh,
                                   (g / 12) * 128, (g % 12) * 64, sm);
    }
}

// ---- gi = h @ W_ih^T + b_ih  [96 blocks] ----
__global__ void __launch_bounds__(256) k_gi(
    const float* __restrict__ W_ih, const float* __restrict__ b_ih) {
    __shared__ __align__(16) float sm[GEMM_SMEM];
    int g = blockIdx.x;
    mma_gemm_body<H3, true, 0>(g_h, W_ih, b_ih, g_gi,
                               (g / 12) * 128, (g % 12) * 64, sm);
}

// ---- y = out @ W_lin + b_lin  [16 blocks] ----
__global__ void __launch_bounds__(256) k_fin(
    const float* __restrict__ W_lin, const float* __restrict__ b_lin,
    float* __restrict__ C) {
    __shared__ __align__(16) float sm[GEMM_SMEM];
    int g = blockIdx.x;
    mma_gemm_body<OUTD, false, 0>(g_out, W_lin, b_lin, C,
                                  (g >> 1) * 128, (g & 1) * 64, sm);
}

// ---------------- k_gate: GRU gate combine + silu --------------------------
__global__ void k_gate() {
    int idx = blockIdx.x * 256 + threadIdx.x;
    int b = idx >> 8, j = idx & 255;
    const float* gi = g_gi + (long)b * H3;
    const float* gh = g_gh + (long)b * H3;
    float r = sigmoidf_(gi[j] + gh[j]);
    float z = sigmoidf_(gi[HH + j] + gh[HH + j]);
    float n = tanhf(gi[2 * HH + j] + r * gh[2 * HH + j]);
    float o = g_out[idx];
    float v = (1.0f - z) * n + z * o;
    g_out[idx] = v * sigmoidf_(v);
}

// ---------------- launch --------------------------------------------------
extern "C" void kernel_launch(void* const* d_in, const int* in_sizes, int n_in,
                              void* d_out, int out_size) {
    const float* x        = (const float*)d_in[0];
    const int*   batch    = (const int*)  d_in[1];
    const float* W        = (const float*)d_in[2];
    const float* att_src  = (const float*)d_in[3];
    const float* att_dst  = (const float*)d_in[4];
    const float* bias_gat = (const float*)d_in[5];
    const float* W_ih     = (const float*)d_in[6];
    const float* W_hh     = (const float*)d_in[7];
    const float* b_ih     = (const float*)d_in[8];
    const float* b_hh     = (const float*)d_in[9];
    const float* W_lin    = (const float*)d_in[10];
    const float* b_lin    = (const float*)d_in[11];
    float* out = (float*)d_out;

    int n = in_sizes[1];

    k_prep<<<32, 256>>>(W, att_src, att_dst);
    k_segoff<<<(BB + 1 + 255) / 256, 256>>>(batch, n);

    // t = 0: fused pooling + attention (sweep2 rides L2)
    k_pass0_attn<<<BB, 256>>>(x);
    k_h_gh<<<32 + 96, 256>>>(W, bias_gat, W_hh, b_hh);
    k_gi<<<96, 256>>>(W_ih, b_ih);
    k_gate<<<BB * HH / 256, 256>>>();

    // t = 1: attention in reverse segment order (L2 tail reuse)
    k_attn_rev<<<BB, 256>>>(x);
    k_h_gh<<<32 + 96, 256>>>(W, bias_gat, W_hh, b_hh);
    k_gi<<<96, 256>>>(W_ih, b_ih);
    k_gate<<<BB * HH / 256, 256>>>();

    k_fin<<<16, 256>>>(W_lin, b_lin, out);
}

// round 17
// speedup vs baseline: 2.2194x; 1.0153x over previous
#include <cuda_runtime.h>
#include <math.h>
#include <stdint.h>

// Problem constants (fixed by the dataset)
#define NN   200000
#define BB   1024
#define HH   256
#define H3   768
#define OUTD 128
#define NEG_SLOPE 0.01f

// ---------------- scratch (device globals; no allocation allowed) ----------
__device__ float g_a_src[NN];
__device__ float g_out [BB * HH];
__device__ float g_wsum[BB * HH];
__device__ float g_h   [BB * HH];
__device__ float g_gi  [BB * H3];
__device__ float g_gh  [BB * H3];
__device__ int   g_segoff[BB + 1];
__device__ float g_was[HH];
__device__ float g_wad[HH];

// ---------------- reductions ----------------
__device__ __forceinline__ float warp_sum(float v) {
    #pragma unroll
    for (int o = 16; o; o >>= 1) v += __shfl_xor_sync(0xffffffffu, v, o);
    return v;
}
__device__ __forceinline__ float warp_max(float v) {
    #pragma unroll
    for (int o = 16; o; o >>= 1) v = fmaxf(v, __shfl_xor_sync(0xffffffffu, v, o));
    return v;
}
__device__ __forceinline__ float block_sum(float v, float* sh) {
    int l = threadIdx.x & 31, w = threadIdx.x >> 5;
    v = warp_sum(v);
    if (l == 0) sh[w] = v;
    __syncthreads();
    if (w == 0) {
        float r = (l < 8) ? sh[l] : 0.0f;
        r = warp_sum(r);
        if (l == 0) sh[0] = r;
    }
    __syncthreads();
    float r = sh[0];
    __syncthreads();
    return r;
}
__device__ __forceinline__ float block_max(float v, float* sh) {
    int l = threadIdx.x & 31, w = threadIdx.x >> 5;
    v = warp_max(v);
    if (l == 0) sh[w] = v;
    __syncthreads();
    if (w == 0) {
        float r = (l < 8) ? sh[l] : -INFINITY;
        r = warp_max(r);
        if (l == 0) sh[0] = r;
    }
    __syncthreads();
    float r = sh[0];
    __syncthreads();
    return r;
}

__device__ __forceinline__ float sigmoidf_(float x) {
    return 1.0f / (1.0f + __expf(-x));
}

// ---------------- k_prep: w_as = W @ att_src, w_ad = W @ att_dst -----------
__global__ void k_prep(const float* __restrict__ W,
                       const float* __restrict__ att_src,
                       const float* __restrict__ att_dst) {
    int w = threadIdx.x >> 5, l = threadIdx.x & 31;
    int row = blockIdx.x * 8 + w;
    const float* Wr = W + (long)row * HH;
    float ps = 0.f, pd = 0.f;
    for (int j = l; j < HH; j += 32) {
        float v = Wr[j];
        ps += v * att_src[j];
        pd += v * att_dst[j];
    }
    ps = warp_sum(ps); pd = warp_sum(pd);
    if (l == 0) { g_was[row] = ps; g_wad[row] = pd; }
}

// ---------------- k_segoff: lower_bound per graph id -----------------------
__global__ void k_segoff(const int* __restrict__ batch, int n) {
    int j = blockIdx.x * blockDim.x + threadIdx.x;
    if (j > BB) return;
    int lo = 0, hi = n;
    while (lo < hi) {
        int mid = (lo + hi) >> 1;
        if (batch[mid] < j) lo = mid + 1; else hi = mid;
    }
    g_segoff[j] = lo;
}

// ---------------- softmax + weighted-sum core ------------------------------
__device__ __forceinline__ void attn_core(const float* __restrict__ x,
                                          int b, int s, int e, float adst,
                                          float* red, float* shr) {
    int tid = threadIdx.x, w = tid >> 5, l = tid & 31;

    float m = -INFINITY, d = 0.f;
    for (int r = s + tid; r < e; r += 256) {
        float ev = g_a_src[r] + adst;
        ev = ev > 0.f ? ev : NEG_SLOPE * ev;
        float mn = fmaxf(m, ev);
        d = d * __expf(m - mn) + __expf(ev - mn);
        m = mn;
    }
    float M = block_max(m, shr);
    float dd = (d > 0.f) ? d * __expf(m - M) : 0.f;
    float D = block_sum(dd, shr);
    float inv = (e > s) ? 1.0f / D : 0.0f;

    float4 acc0 = make_float4(0.f, 0.f, 0.f, 0.f);
    float4 acc1 = make_float4(0.f, 0.f, 0.f, 0.f);
    int r = s + w;
    for (; r + 8 < e; r += 16) {
        float e0 = g_a_src[r] + adst;
        float e1 = g_a_src[r + 8] + adst;
        e0 = e0 > 0.f ? e0 : NEG_SLOPE * e0;
        e1 = e1 > 0.f ? e1 : NEG_SLOPE * e1;
        float al0 = __expf(e0 - M) * inv;
        float al1 = __expf(e1 - M) * inv;
        const float4* x0 = (const float4*)(x + (long)r * HH);
        const float4* x1 = (const float4*)(x + (long)(r + 8) * HH);
        float4 a0 = x0[l], c0 = x0[l + 32];
        float4 a1 = x1[l], c1 = x1[l + 32];
        acc0.x += al0 * a0.x + al1 * a1.x; acc0.y += al0 * a0.y + al1 * a1.y;
        acc0.z += al0 * a0.z + al1 * a1.z; acc0.w += al0 * a0.w + al1 * a1.w;
        acc1.x += al0 * c0.x + al1 * c1.x; acc1.y += al0 * c0.y + al1 * c1.y;
        acc1.z += al0 * c0.z + al1 * c1.z; acc1.w += al0 * c0.w + al1 * c1.w;
    }
    if (r < e) {
        float e0 = g_a_src[r] + adst;
        e0 = e0 > 0.f ? e0 : NEG_SLOPE * e0;
        float al0 = __expf(e0 - M) * inv;
        const float4* x0 = (const float4*)(x + (long)r * HH);
        float4 a0 = x0[l], c0 = x0[l + 32];
        acc0.x += al0 * a0.x; acc0.y += al0 * a0.y;
        acc0.z += al0 * a0.z; acc0.w += al0 * a0.w;
        acc1.x += al0 * c0.x; acc1.y += al0 * c0.y;
        acc1.z += al0 * c0.z; acc1.w += al0 * c0.w;
    }
    float4* redw = (float4*)(red + w * HH);
    redw[l] = acc0;
    redw[l + 32] = acc1;
    __syncthreads();
    float sum = 0.f;
    #pragma unroll
    for (int ww = 0; ww < 8; ww++) sum += red[ww * HH + tid];
    g_wsum[(long)b * HH + tid] = sum;
}

// ---------------- k_pass0_attn: fused pool + t=0 attention -----------------
__global__ void __launch_bounds__(256) k_pass0_attn(const float* __restrict__ x) {
    __shared__ __align__(16) float red[8 * HH];
    __shared__ float shr[32];
    int b = blockIdx.x;
    int tid = threadIdx.x, w = tid >> 5, l = tid & 31;
    int s = g_segoff[b], e = g_segoff[b + 1];

    const float4* was4 = (const float4*)g_was;
    float4 wa = was4[l], wb = was4[l + 32];

    float4 acc0 = make_float4(0.f, 0.f, 0.f, 0.f);
    float4 acc1 = make_float4(0.f, 0.f, 0.f, 0.f);

    int r = s + w;
    for (; r + 8 < e; r += 16) {
        const float4* x0 = (const float4*)(x + (long)r * HH);
        const float4* x1 = (const float4*)(x + (long)(r + 8) * HH);
        float4 a0 = x0[l], c0 = x0[l + 32];
        float4 a1 = x1[l], c1 = x1[l + 32];
        acc0.x += a0.x + a1.x; acc0.y += a0.y + a1.y;
        acc0.z += a0.z + a1.z; acc0.w += a0.w + a1.w;
        acc1.x += c0.x + c1.x; acc1.y += c0.y + c1.y;
        acc1.z += c0.z + c1.z; acc1.w += c0.w + c1.w;
        float p0 = a0.x * wa.x + a0.y * wa.y + a0.z * wa.z + a0.w * wa.w
                 + c0.x * wb.x + c0.y * wb.y + c0.z * wb.z + c0.w * wb.w;
        float p1 = a1.x * wa.x + a1.y * wa.y + a1.z * wa.z + a1.w * wa.w
                 + c1.x * wb.x + c1.y * wb.y + c1.z * wb.z + c1.w * wb.w;
        p0 = warp_sum(p0);
        p1 = warp_sum(p1);
        if (l == 0) { g_a_src[r] = p0; g_a_src[r + 8] = p1; }
    }
    if (r < e) {
        const float4* x0 = (const float4*)(x + (long)r * HH);
        float4 a0 = x0[l], c0 = x0[l + 32];
        acc0.x += a0.x; acc0.y += a0.y; acc0.z += a0.z; acc0.w += a0.w;
        acc1.x += c0.x; acc1.y += c0.y; acc1.z += c0.z; acc1.w += c0.w;
        float p0 = a0.x * wa.x + a0.y * wa.y + a0.z * wa.z + a0.w * wa.w
                 + c0.x * wb.x + c0.y * wb.y + c0.z * wb.z + c0.w * wb.w;
        p0 = warp_sum(p0);
        if (l == 0) g_a_src[r] = p0;
    }
    float4* redw = (float4*)(red + w * HH);
    redw[l] = acc0;
    redw[l + 32] = acc1;
    __syncthreads();
    float sum = 0.f;
    #pragma unroll
    for (int ww = 0; ww < 8; ww++) sum += red[ww * HH + tid];
    g_out[(long)b * HH + tid] = sum;

    float adst = block_sum(sum * g_wad[tid], shr);
    attn_core(x, b, s, e, adst, red, shr);
}

// ---------------- k_attn_rev: t=1 attention, reversed segment order --------
__global__ void __launch_bounds__(256, 6) k_attn_rev(const float* __restrict__ x) {
    __shared__ __align__(16) float red[8 * HH];
    __shared__ float shr[32];
    int b = (BB - 1) - blockIdx.x;
    int tid = threadIdx.x;
    int s = g_segoff[b], e = g_segoff[b + 1];

    float adst = block_sum(g_out[(long)b * HH + tid] * g_wad[tid], shr);
    attn_core(x, b, s, e, adst, red, shr);
}

// ================= tf32 tensor-core GEMM (3-stage cp.async) ===============
// C[1024, Nn] = A[1024, 256] * B (+bias, epilogue)
// BM=64, BN=64, BK=16; 128 threads = 4 warps (2x2), warp tile 32x32.
// smem holds raw fp32 (cp.async), tf32 conversion at fragment load.
// TRANSB=true : B stored [Nn, 256] row-major (op = A @ B^T), smem [n][k]
// TRANSB=false: B stored [256, Nn] row-major,               smem [k][n]
#define GK    16
#define LDA_  20               // A smem row stride ([m][k] + pad)
#define LDBT  20               // B smem stride, TRANSB layout [n][k]
#define LDBN  72               // B smem stride, !TRANSB layout [k][n] (72%32=8)
#define ASTG  (64 * LDA_)      // 1280 floats / stage
#define BSTG  (64 * LDBT)      // 1280 floats / stage (>= 16*LDBN = 1152)
#define STG   (ASTG + BSTG)    // 2560 floats / stage; 3 stages = 30 KB

__device__ __forceinline__ uint32_t tf32_(float x) {
    uint32_t r;
    asm("cvt.rna.tf32.f32 %0, %1;" : "=r"(r) : "f"(x));
    return r;
}
__device__ __forceinline__ void mma8(float* c, const uint32_t* a, const uint32_t* b) {
    asm("mma.sync.aligned.m16n8k8.row.col.f32.tf32.tf32.f32 "
        "{%0,%1,%2,%3}, {%4,%5,%6,%7}, {%8,%9}, {%0,%1,%2,%3};"
        : "+f"(c[0]), "+f"(c[1]), "+f"(c[2]), "+f"(c[3])
        : "r"(a[0]), "r"(a[1]), "r"(a[2]), "r"(a[3]), "r"(b[0]), "r"(b[1]));
}
__device__ __forceinline__ void cp16(float* dst, const float* src) {
    uint32_t da = (uint32_t)__cvta_generic_to_shared(dst);
    asm volatile("cp.async.cg.shared.global [%0], [%1], 16;" :: "r"(da), "l"(src));
}
__device__ __forceinline__ void cp_commit() {
    asm volatile("cp.async.commit_group;");
}
template <int N> __device__ __forceinline__ void cp_wait() {
    asm volatile("cp.async.wait_group %0;" :: "n"(N));
}

// Issue one BK=16 stage: A tile 64x16, B tile (64x16 | 16x64). 128 threads.
template <int Nn, bool TRANSB>
__device__ __forceinline__ void issue_stage(
    float* Sa, float* Sb, const float* __restrict__ A, const float* __restrict__ Bw,
    int bm, int bn, int k0) {
    const int K = HH;
    int tid = threadIdx.x;
    #pragma unroll
    for (int q = 0; q < 2; q++) {                 // A: 256 16B-chunks
        int c = tid + q * 128, row = c >> 2, c4 = c & 3;
        cp16(Sa + row * LDA_ + c4 * 4, A + (long)(bm + row) * K + k0 + c4 * 4);
    }
    #pragma unroll
    for (int q = 0; q < 2; q++) {                 // B: 256 16B-chunks
        int c = tid + q * 128;
        if (TRANSB) {                              // [n][k]
            int nrow = c >> 2, c4 = c & 3;
            cp16(Sb + nrow * LDBT + c4 * 4, Bw + (long)(bn + nrow) * K + k0 + c4 * 4);
        } else {                                   // [k][n]
            int k = c >> 4, c4 = c & 15;
            cp16(Sb + k * LDBN + c4 * 4, Bw + (long)(k0 + k) * Nn + bn + c4 * 4);
        }
    }
    cp_commit();
}

template <int Nn, bool TRANSB>
__device__ __forceinline__ void consume_stage(
    const float* Ac, const float* Bc, float acc[2][4][4], int ln, int wm, int wn) {
    #pragma unroll
    for (int k8 = 0; k8 < GK; k8 += 8) {
        uint32_t af[2][4], bf[4][2];
        #pragma unroll
        for (int mi = 0; mi < 2; mi++) {
            int mr = wm + mi * 16 + (ln >> 2);
            af[mi][0] = tf32_(Ac[mr * LDA_ + k8 + (ln & 3)]);
            af[mi][1] = tf32_(Ac[(mr + 8) * LDA_ + k8 + (ln & 3)]);
            af[mi][2] = tf32_(Ac[mr * LDA_ + k8 + 4 + (ln & 3)]);
            af[mi][3] = tf32_(Ac[(mr + 8) * LDA_ + k8 + 4 + (ln & 3)]);
        }
        #pragma unroll
        for (int ni = 0; ni < 4; ni++) {
            int nr = wn + ni * 8 + (ln >> 2);
            if (TRANSB) {
                bf[ni][0] = tf32_(Bc[nr * LDBT + k8 + (ln & 3)]);
                bf[ni][1] = tf32_(Bc[nr * LDBT + k8 + 4 + (ln & 3)]);
            } else {
                bf[ni][0] = tf32_(Bc[(k8 + (ln & 3)) * LDBN + nr]);
                bf[ni][1] = tf32_(Bc[(k8 + 4 + (ln & 3)) * LDBN + nr]);
            }
        }
        #pragma unroll
        for (int mi = 0; mi < 2; mi++)
            #pragma unroll
            for (int ni = 0; ni < 4; ni++)
                mma8(acc[mi][ni], af[mi], bf[ni]);
    }
}

template <int Nn, bool TRANSB, int EPI>
__device__ __forceinline__ void mma_gemm_body(
    const float* __restrict__ A, const float* __restrict__ Bw,
    const float* __restrict__ bias, float* __restrict__ C,
    int bm, int bn, float* sm) {

    const int K = HH, NIT = K / GK;      // 16 iterations
    int tid = threadIdx.x, ln = tid & 31, w = tid >> 5;
    int wm = (w >> 1) * 32, wn = (w & 1) * 32;

    float acc[2][4][4];
    #pragma unroll
    for (int i = 0; i < 2; i++)
        #pragma unroll
        for (int j = 0; j < 4; j++)
            #pragma unroll
            for (int q = 0; q < 4; q++) acc[i][j][q] = 0.f;

    // prologue: stages 0, 1 in flight
    issue_stage<Nn, TRANSB>(sm, sm + ASTG, A, Bw, bm, bn, 0);
    issue_stage<Nn, TRANSB>(sm + STG, sm + STG + ASTG, A, Bw, bm, bn, GK);

    #pragma unroll
    for (int i = 0; i < NIT - 1; i++) {
        cp_wait<1>();            // stage i landed
        __syncthreads();         // all warps past iter i-1 reads
        if (i + 2 < NIT) {
            int st = (i + 2) % 3;
            issue_stage<Nn, TRANSB>(sm + st * STG, sm + st * STG + ASTG,
                                    A, Bw, bm, bn, (i + 2) * GK);
        }
        int cs = i % 3;
        consume_stage<Nn, TRANSB>(sm + cs * STG, sm + cs * STG + ASTG,
                                  acc, ln, wm, wn);
    }
    cp_wait<0>();
    __syncthreads();
    {
        int cs = (NIT - 1) % 3;
        consume_stage<Nn, TRANSB>(sm + cs * STG, sm + cs * STG + ASTG,
                                  acc, ln, wm, wn);
    }

    // epilogue
    #pragma unroll
    for (int mi = 0; mi < 2; mi++) {
        #pragma unroll
        for (int ni = 0; ni < 4; ni++) {
            int m = bm + wm + mi * 16 + (ln >> 2);
            int n = bn + wn + ni * 8 + (ln & 3) * 2;
            float b0 = bias[n], b1 = bias[n + 1];
            float v0 = acc[mi][ni][0] + b0, v1 = acc[mi][ni][1] + b1;
            float v2 = acc[mi][ni][2] + b0, v3 = acc[mi][ni][3] + b1;
            if (EPI == 1) {
                v0 = (v0 > 0.f) ? v0 : expm1f(v0);
                v1 = (v1 > 0.f) ? v1 : expm1f(v1);
                v2 = (v2 > 0.f) ? v2 : expm1f(v2);
                v3 = (v3 > 0.f) ? v3 : expm1f(v3);
            }
            *(float2*)(C + (long)m * Nn + n)       = make_float2(v0, v1);
            *(float2*)(C + (long)(m + 8) * Nn + n) = make_float2(v2, v3);
        }
    }
}

#define GEMM_SMEM (3 * STG)   // 7680 floats = 30 KB

// ---- fused (homogeneous GEMM bodies, both depend only on pass0/gate):
//      blocks [0,64):    h  = elu(wsum @ W + bias_gat)   16m x 4n
//      blocks [64,256):  gh = out @ W_hh^T + b_hh        16m x 12n
__global__ void __launch_bounds__(128) k_h_gh(
    const float* __restrict__ W, const float* __restrict__ bias_gat,
    const float* __restrict__ W_hh, const float* __restrict__ b_hh) {
    __shared__ __align__(16) float sm[GEMM_SMEM];
    if (blockIdx.x < 64) {
        int g = blockIdx.x;
        mma_gemm_body<HH, false, 1>(g_wsum, W, bias_gat, g_h,
                                    (g >> 2) * 64, (g & 3) * 64, sm);
    } else {
        int g = blockIdx.x - 64;
        mma_gemm_body<H3, true, 0>(g_out, W_hh, b_hh, g_gh,
                                   (g / 12) * 64, (g % 12) * 64, sm);
    }
}

// ---- gi = h @ W_ih^T + b_ih  [192 blocks: 16m x 12n] ----
__global__ void __launch_bounds__(128) k_gi(
    const float* __restrict__ W_ih, const float* __restrict__ b_ih) {
    __shared__ __align__(16) float sm[GEMM_SMEM];
    int g = blockIdx.x;
    mma_gemm_body<H3, true, 0>(g_h, W_ih, b_ih, g_gi,
                               (g / 12) * 64, (g % 12) * 64, sm);
}

// ---- y = out @ W_lin + b_lin  [32 blocks: 16m x 2n] ----
__global__ void __launch_bounds__(128) k_fin(
    const float* __restrict__ W_lin, const float* __restrict__ b_lin,
    float* __restrict__ C) {
    __shared__ __align__(16) float sm[GEMM_SMEM];
    int g = blockIdx.x;
    mma_gemm_body<OUTD, false, 0>(g_out, W_lin, b_lin, C,
                                  (g >> 1) * 64, (g & 1) * 64, sm);
}

// ---------------- k_gate: GRU gate combine + silu (float4) -----------------
__global__ void k_gate() {
    int idx4 = blockIdx.x * 256 + threadIdx.x;   // BB*HH/4 = 65536 float4s
    int b = idx4 >> 6, j4 = idx4 & 63;           // 64 float4 per 256-col row
    const float4* gi = (const float4*)(g_gi + (long)b * H3);
    const float4* gh = (const float4*)(g_gh + (long)b * H3);
    float4 giR = gi[j4],       ghR = gh[j4];
    float4 giZ = gi[64 + j4],  ghZ = gh[64 + j4];
    float4 giN = gi[128 + j4], ghN = gh[128 + j4];
    float4 o = ((const float4*)g_out)[idx4];
    float4 res;
    {
        float r = sigmoidf_(giR.x + ghR.x);
        float z = sigmoidf_(giZ.x + ghZ.x);
        float n = tanhf(giN.x + r * ghN.x);
        float v = (1.0f - z) * n + z * o.x;
        res.x = v * sigmoidf_(v);
    }
    {
        float r = sigmoidf_(giR.y + ghR.y);
        float z = sigmoidf_(giZ.y + ghZ.y);
        float n = tanhf(giN.y + r * ghN.y);
        float v = (1.0f - z) * n + z * o.y;
        res.y = v * sigmoidf_(v);
    }
    {
        float r = sigmoidf_(giR.z + ghR.z);
        float z = sigmoidf_(giZ.z + ghZ.z);
        float n = tanhf(giN.z + r * ghN.z);
        float v = (1.0f - z) * n + z * o.z;
        res.z = v * sigmoidf_(v);
    }
    {
        float r = sigmoidf_(giR.w + ghR.w);
        float z = sigmoidf_(giZ.w + ghZ.w);
        float n = tanhf(giN.w + r * ghN.w);
        float v = (1.0f - z) * n + z * o.w;
        res.w = v * sigmoidf_(v);
    }
    ((float4*)g_out)[idx4] = res;
}

// ---------------- launch (single stream — proven graph-capturable) --------
extern "C" void kernel_launch(void* const* d_in, const int* in_sizes, int n_in,
                              void* d_out, int out_size) {
    const float* x        = (const float*)d_in[0];
    const int*   batch    = (const int*)  d_in[1];
    const float* W        = (const float*)d_in[2];
    const float* att_src  = (const float*)d_in[3];
    const float* att_dst  = (const float*)d_in[4];
    const float* bias_gat = (const float*)d_in[5];
    const float* W_ih     = (const float*)d_in[6];
    const float* W_hh     = (const float*)d_in[7];
    const float* b_ih     = (const float*)d_in[8];
    const float* b_hh     = (const float*)d_in[9];
    const float* W_lin    = (const float*)d_in[10];
    const float* b_lin    = (const float*)d_in[11];
    float* out = (float*)d_out;

    int n = in_sizes[1];

    k_prep<<<32, 256>>>(W, att_src, att_dst);
    k_segoff<<<(BB + 1 + 255) / 256, 256>>>(batch, n);

    // ---- t = 0 ----
    k_pass0_attn<<<BB, 256>>>(x);                 // out, a_src, wsum
    k_h_gh<<<256, 128>>>(W, bias_gat, W_hh, b_hh);// h + gh (homogeneous fuse)
    k_gi<<<192, 128>>>(W_ih, b_ih);               // gi = h@W_ih^T
    k_gate<<<BB * HH / 1024, 256>>>();            // out update

    // ---- t = 1 ----
    k_attn_rev<<<BB, 256>>>(x);                   // wsum (reverse order, L2 tail)
    k_h_gh<<<256, 128>>>(W, bias_gat, W_hh, b_hh);
    k_gi<<<192, 128>>>(W_ih, b_ih);
    k_gate<<<BB * HH / 1024, 256>>>();

    k_fin<<<32, 128>>>(W_lin, b_lin, out);        // final projection
}